// round 13
// baseline (speedup 1.0000x reference)
#include <cuda_runtime.h>
#include <cuda_bf16.h>
#include <math.h>
#include <stdint.h>

#define BATCH 4096
#define FDIM  512
#define NJ    16
#define NM    64
#define NU    512
#define JM    (NJ*NM)   // 1024

// ---- scratch (device globals; no allocation allowed) ----
__device__ __nv_bfloat16 g_hb[(size_t)BATCH * FDIM];   // 4 MB
__device__ __nv_bfloat16 g_db[(size_t)JM * FDIM];      // 1 MB
__device__ __nv_bfloat16 g_Wb[(size_t)JM * NU];        // 1 MB
__device__ __nv_bfloat16 g_A2[(size_t)BATCH * JM];     // 8 MB : e-scaled Khd
__device__ float g_h2[BATCH];
__device__ float g_d2[JM];
__device__ float g_kdd[NJ];
__device__ int   g_kdd_flag[NJ];
__device__ int   g_band[BATCH / 128];
__device__ float g_e[BATCH * NJ];
__device__ float g_Z[BATCH];

// ================= PTX helpers =================
__device__ __forceinline__ void cp16(uint32_t dst, const void* src) {
    asm volatile("cp.async.cg.shared.global [%0], [%1], 16;\n" :: "r"(dst), "l"(src));
}
__device__ __forceinline__ void cp_commit() { asm volatile("cp.async.commit_group;\n"); }
template <int N> __device__ __forceinline__ void cp_wait() {
    asm volatile("cp.async.wait_group %0;\n" :: "n"(N));
}
__device__ __forceinline__ void ldm_x4(uint32_t a[4], uint32_t addr) {
    asm volatile("ldmatrix.sync.aligned.m8n8.x4.shared.b16 {%0,%1,%2,%3}, [%4];\n"
                 : "=r"(a[0]), "=r"(a[1]), "=r"(a[2]), "=r"(a[3]) : "r"(addr));
}
__device__ __forceinline__ void ldm_x4t(uint32_t a[4], uint32_t addr) {
    asm volatile("ldmatrix.sync.aligned.m8n8.x4.trans.shared.b16 {%0,%1,%2,%3}, [%4];\n"
                 : "=r"(a[0]), "=r"(a[1]), "=r"(a[2]), "=r"(a[3]) : "r"(addr));
}
__device__ __forceinline__ void mma_bf16(float c[4], const uint32_t a[4], uint32_t b0, uint32_t b1) {
    asm volatile(
        "mma.sync.aligned.m16n8k16.row.col.f32.bf16.bf16.f32 "
        "{%0,%1,%2,%3}, {%4,%5,%6,%7}, {%8,%9}, {%0,%1,%2,%3};\n"
        : "+f"(c[0]), "+f"(c[1]), "+f"(c[2]), "+f"(c[3])
        : "r"(a[0]), "r"(a[1]), "r"(a[2]), "r"(a[3]), "r"(b0), "r"(b1));
}

// ================= prep: streaming convert + sumsq + zero flags ==========
__global__ void __launch_bounds__(256) prep_kernel(const float* __restrict__ h,
                                                   const float* __restrict__ dom,
                                                   const float* __restrict__ W) {
    int warp = (blockIdx.x << 3) + (threadIdx.x >> 5);
    int lane = threadIdx.x & 31;
    if (blockIdx.x == 0 && threadIdx.x < NJ) g_kdd_flag[threadIdx.x] = 0;
    if (blockIdx.x == 1 && threadIdx.x < BATCH / 128) g_band[threadIdx.x] = 0;
    const float* p;
    __nv_bfloat16* dst;
    float* o = nullptr;
    if (warp < BATCH) {
        p = h + (size_t)warp * FDIM; dst = g_hb + (size_t)warp * FDIM; o = &g_h2[warp];
        if (lane == 0) g_Z[warp] = 0.f;
    } else if (warp < BATCH + JM) {
        int r = warp - BATCH;
        p = dom + (size_t)r * FDIM; dst = g_db + (size_t)r * FDIM; o = &g_d2[r];
    } else {
        int r = warp - BATCH - JM;
        p = W + (size_t)r * NU; dst = g_Wb + (size_t)r * NU;
    }
    float s = 0.f;
    #pragma unroll
    for (int i = 0; i < 4; i++) {
        int idx = (lane + i * 32) << 2;
        float4 v = *(const float4*)&p[idx];
        __nv_bfloat162 o0 = __floats2bfloat162_rn(v.x, v.y);
        __nv_bfloat162 o1 = __floats2bfloat162_rn(v.z, v.w);
        uint2 u; u.x = *(uint32_t*)&o0; u.y = *(uint32_t*)&o1;
        *(uint2*)&dst[idx] = u;
        s += v.x*v.x + v.y*v.y + v.z*v.z + v.w*v.w;
    }
    if (o) {
        #pragma unroll
        for (int off = 16; off; off >>= 1) s += __shfl_xor_sync(0xffffffffu, s, off);
        if (lane == 0) *o = s;
    }
}

// ====== fused launch: [0,16)=kdd, [16,272)=gemm1 tiles, [272,528)=gemm2 ===
__global__ void __launch_bounds__(256, 2) fused_kernel(const float* __restrict__ bvec,
                                                       float* __restrict__ out) {
    extern __shared__ char smem[];          // 48 KB dynamic (stage buffers)
    __shared__ float jp[128][2];
    __shared__ float es[128][2];
    __shared__ float kddm[2];
    __shared__ float d2s[NM];
    __shared__ float ws[4];
    __shared__ __align__(16) __nv_bfloat16 Ae[128][24];
    __shared__ __align__(16) __nv_bfloat16 Be[64][24];
    const int bid = blockIdx.x;
    const int tid = threadIdx.x;
    const int lane = tid & 31, wid = tid >> 5;
    uint32_t base = (uint32_t)__cvta_generic_to_shared(smem);
    const int rlo = lane & 15, chi = lane >> 4;

    if (bid < NJ) {
        // ---------------- kdd block ----------------
        const int j = bid;
        const __nv_bfloat16* dj = g_db + (size_t)j * NM * FDIM;
        if (tid < NM) d2s[tid] = g_d2[j * NM + tid];
        float acc[8][4] = {};
        #pragma unroll 1
        for (int pass = 0; pass < 2; pass++) {
            #pragma unroll
            for (int i = 0; i < 8; i++) {
                int lin = tid + i * 256;
                int r = lin >> 5, c = lin & 31;
                cp16(base + r * 512 + ((c ^ (r & 7)) << 4),
                     dj + (size_t)r * FDIM + pass * 256 + c * 8);
            }
            cp_commit();
            cp_wait<0>();
            __syncthreads();
            if (wid < 4) {
                #pragma unroll 4
                for (int kk = 0; kk < 16; kk++) {
                    int ch = kk * 2 + chi;
                    uint32_t a[4], b[4][4];
                    {
                        int row = wid * 16 + rlo;
                        ldm_x4(a, base + row * 512 + ((ch ^ (row & 7)) << 4));
                    }
                    #pragma unroll
                    for (int nb = 0; nb < 4; nb++) {
                        int row = nb * 16 + rlo;
                        ldm_x4(b[nb], base + row * 512 + ((ch ^ (row & 7)) << 4));
                    }
                    #pragma unroll
                    for (int nb = 0; nb < 4; nb++) {
                        mma_bf16(acc[2*nb],   a, b[nb][0], b[nb][2]);
                        mma_bf16(acc[2*nb+1], a, b[nb][1], b[nb][3]);
                    }
                }
            }
            __syncthreads();
        }
        if (wid < 4) {
            const int qr = lane >> 2;
            const int qc = (lane & 3) * 2;
            int m0 = wid * 16 + qr;
            float d2a = d2s[m0], d2b = d2s[m0 + 8];
            float s = 0.f;
            #pragma unroll
            for (int nt = 0; nt < 8; nt++) {
                int n = nt * 8 + qc;
                float d2x = d2s[n], d2y = d2s[n + 1];
                float* c = acc[nt];
                s += expf(-2.f * (d2a + d2x - 2.f * c[0]));
                s += expf(-2.f * (d2a + d2y - 2.f * c[1]));
                s += expf(-2.f * (d2b + d2x - 2.f * c[2]));
                s += expf(-2.f * (d2b + d2y - 2.f * c[3]));
            }
            #pragma unroll
            for (int off = 16; off; off >>= 1) s += __shfl_xor_sync(0xffffffffu, s, off);
            if (lane == 0) ws[wid] = s;
        }
        __syncthreads();
        if (tid == 0) {
            g_kdd[j] = (ws[0] + ws[1] + ws[2] + ws[3]) * (1.0f / (NM * NM));
            __threadfence();
            atomicExch(&g_kdd_flag[j], 1);
        }
        return;
    }

    if (bid < NJ + 256) {
        // ---------------- gemm1 tile block ----------------
        const int t = bid - NJ;
        const int bx = t & 7, by = t >> 3;
        const int wm = (wid >> 2) * 64;
        const int wn = (wid & 3) * 32;
        const int m0 = by * 128;
        const int n0 = bx * 128;
        const int j0 = bx * 2;

        if (tid < 256) { jp[tid >> 1][tid & 1] = 0.f; }

        int arow[4], asw[4], brow[2], bsw[2];
        #pragma unroll
        for (int im = 0; im < 4; im++) { arow[im] = wm + im * 16 + rlo; asw[im] = (arow[im] >> 1) & 3; }
        #pragma unroll
        for (int ib = 0; ib < 2; ib++) { brow[ib] = wn + ib * 16 + rlo; bsw[ib] = (brow[ib] >> 1) & 3; }

        float acc[4][4][4] = {};

        auto load_stage = [&](int ki, int s) {
            const __nv_bfloat16* ha = g_hb + (size_t)m0 * FDIM + ki * 32;
            const __nv_bfloat16* da = g_db + (size_t)n0 * FDIM + ki * 32;
            uint32_t a_s = base + s * 16384;
            uint32_t b_s = a_s + 8192;
            #pragma unroll
            for (int i = 0; i < 2; i++) {
                int lin = tid + i * 256;
                int r = lin >> 2, c = lin & 3;
                uint32_t off = (uint32_t)(r * 64 + (((c ^ ((r >> 1) & 3))) << 4));
                cp16(a_s + off, ha + (size_t)r * FDIM + c * 8);
                cp16(b_s + off, da + (size_t)r * FDIM + c * 8);
            }
            cp_commit();
        };

        auto compute = [&](int s) {
            uint32_t a_s = base + s * 16384;
            uint32_t b_s = a_s + 8192;
            #pragma unroll
            for (int kk = 0; kk < 2; kk++) {
                int ch = kk * 2 + chi;
                uint32_t a[4][4], b[2][4];
                #pragma unroll
                for (int im = 0; im < 4; im++)
                    ldm_x4(a[im], a_s + arow[im] * 64 + ((ch ^ asw[im]) << 4));
                #pragma unroll
                for (int ib = 0; ib < 2; ib++)
                    ldm_x4(b[ib], b_s + brow[ib] * 64 + ((ch ^ bsw[ib]) << 4));
                #pragma unroll
                for (int im = 0; im < 4; im++) {
                    mma_bf16(acc[im][0], a[im], b[0][0], b[0][2]);
                    mma_bf16(acc[im][1], a[im], b[0][1], b[0][3]);
                    mma_bf16(acc[im][2], a[im], b[1][0], b[1][2]);
                    mma_bf16(acc[im][3], a[im], b[1][1], b[1][3]);
                }
            }
        };

        load_stage(0, 0);
        load_stage(1, 1);
        #pragma unroll 1
        for (int ki = 0; ki < 16; ki++) {
            if (ki < 15) cp_wait<1>(); else cp_wait<0>();
            __syncthreads();
            if (ki + 2 < 16) load_stage(ki + 2, (ki + 2) % 3);
            compute(ki % 3);
        }

        const int qr = lane >> 2;
        const int qc = (lane & 3) * 2;
        const int jj = wn >> 6;
        #pragma unroll
        for (int im = 0; im < 4; im++) {
            int r0g = m0 + wm + im * 16 + qr;
            float h2a = g_h2[r0g], h2b = g_h2[r0g + 8];
            float rs0 = 0.f, rs1 = 0.f;
            #pragma unroll
            for (int in = 0; in < 4; in++) {
                int cg = n0 + wn + in * 8 + qc;
                float d2x = g_d2[cg], d2y = g_d2[cg + 1];
                float* c = acc[im][in];
                c[0] = expf(4.f * c[0] - 2.f * (h2a + d2x));
                c[1] = expf(4.f * c[1] - 2.f * (h2a + d2y));
                c[2] = expf(4.f * c[2] - 2.f * (h2b + d2x));
                c[3] = expf(4.f * c[3] - 2.f * (h2b + d2y));
                rs0 += c[0] + c[1];
                rs1 += c[2] + c[3];
            }
            rs0 += __shfl_xor_sync(0xffffffffu, rs0, 1);
            rs0 += __shfl_xor_sync(0xffffffffu, rs0, 2);
            rs1 += __shfl_xor_sync(0xffffffffu, rs1, 1);
            rs1 += __shfl_xor_sync(0xffffffffu, rs1, 2);
            if ((lane & 3) == 0) {
                atomicAdd(&jp[wm + im * 16 + qr][jj], rs0);
                atomicAdd(&jp[wm + im * 16 + qr + 8][jj], rs1);
            }
        }
        if (tid < 2) {
            while (atomicAdd(&g_kdd_flag[j0 + tid], 0) == 0) { }
            kddm[tid] = *((volatile float*)&g_kdd[j0 + tid]);
        }
        __syncthreads();
        if (tid < 256) {
            int rl = tid >> 1, j = tid & 1;
            float jsum = jp[rl][j];
            float e = expf(jsum * (1.0f / 32.0f) - 1.0f - kddm[j]);
            es[rl][j] = e;
            g_e[(m0 + rl) * NJ + j0 + j] = e;
            atomicAdd(&g_Z[m0 + rl], e);
        }
        __syncthreads();
        #pragma unroll
        for (int im = 0; im < 4; im++) {
            int rl = wm + im * 16 + qr;
            int r0g = m0 + rl;
            float e0 = es[rl][jj], e1 = es[rl + 8][jj];
            #pragma unroll
            for (int in = 0; in < 4; in++) {
                int cg = n0 + wn + in * 8 + qc;
                float* c = acc[im][in];
                *(__nv_bfloat162*)&g_A2[(size_t)r0g * JM + cg] =
                    __floats2bfloat162_rn(c[0] * e0, c[1] * e0);
                *(__nv_bfloat162*)&g_A2[(size_t)(r0g + 8) * JM + cg] =
                    __floats2bfloat162_rn(c[2] * e1, c[3] * e1);
            }
        }
        __syncthreads();
        if (tid == 0) {
            __threadfence();
            atomicAdd(&g_band[by], 1);
        }
        return;
    }

    // ---------------- gemm2 tile block (BK=32, 3-stage) ----------------
    {
        const int t = bid - NJ - 256;
        const int nx = t & 7, my = t >> 3;
        const int wm = (wid >> 1) * 32;    // 4 m bands of 32
        const int wn = (wid & 1) * 32;     // 2 n bands of 32
        const int m0 = my * 128;
        const int n0 = nx * 64;

        // wait for all 8 gemm1 tiles of this m band
        if (tid == 0) {
            while (atomicAdd(&g_band[my], 0) < 8) { }
        }
        __syncthreads();
        __threadfence();

        // stage e (bf16) and bvec^T (bf16)
        for (int idx = tid; idx < 128 * 16; idx += 256) {
            int rr = idx >> 4, j = idx & 15;
            Ae[rr][j] = __float2bfloat16(*((volatile float*)&g_e[(size_t)(m0 + rr) * NJ + j]));
            if (rr < 64) Be[rr][j] = __float2bfloat16(bvec[(size_t)j * NU + n0 + rr]);
        }

        uint32_t Bs_base = base + 24576;   // A: 3x8192 at 0, B: 3x4096 at 24576
        uint32_t Ae_base = (uint32_t)__cvta_generic_to_shared(Ae);
        uint32_t Be_base = (uint32_t)__cvta_generic_to_shared(Be);

        int arow[2], asw[2];
        #pragma unroll
        for (int im = 0; im < 2; im++) { arow[im] = wm + im * 16 + rlo; asw[im] = (arow[im] >> 1) & 3; }

        float acc[2][4][4] = {};

        auto load_stage = [&](int ki, int s) {
            const __nv_bfloat16* asrc = g_A2 + (size_t)m0 * JM + ki * 32;
            const __nv_bfloat16* bsrc = g_Wb + (size_t)ki * 32 * NU + n0;
            uint32_t a_s = base + s * 8192;
            uint32_t b_s = Bs_base + s * 4096;
            #pragma unroll
            for (int i = 0; i < 2; i++) {
                int lin = tid + i * 256;
                int r = lin >> 2, c = lin & 3;
                cp16(a_s + r * 64 + ((c ^ ((r >> 1) & 3)) << 4),
                     asrc + (size_t)r * JM + c * 8);
            }
            {
                int r = tid >> 3, c = tid & 7;   // 32 rows x 8 chunks
                cp16(b_s + r * 128 + ((c ^ (r & 7)) << 4),
                     bsrc + (size_t)r * NU + c * 8);
            }
            cp_commit();
        };

        auto compute = [&](int s) {
            uint32_t a_s = base + s * 8192;
            uint32_t b_s = Bs_base + s * 4096;
            #pragma unroll
            for (int kk = 0; kk < 2; kk++) {
                int ch = kk * 2 + chi;
                uint32_t a[2][4], b[2][4];
                #pragma unroll
                for (int im = 0; im < 2; im++)
                    ldm_x4(a[im], a_s + arow[im] * 64 + ((ch ^ asw[im]) << 4));
                #pragma unroll
                for (int ib = 0; ib < 2; ib++) {
                    int row = kk * 16 + rlo;
                    int cb = (wn >> 3) + ib * 2 + chi;
                    ldm_x4t(b[ib], b_s + row * 128 + ((cb ^ (row & 7)) << 4));
                }
                #pragma unroll
                for (int im = 0; im < 2; im++) {
                    mma_bf16(acc[im][0], a[im], b[0][0], b[0][1]);
                    mma_bf16(acc[im][1], a[im], b[0][2], b[0][3]);
                    mma_bf16(acc[im][2], a[im], b[1][0], b[1][1]);
                    mma_bf16(acc[im][3], a[im], b[1][2], b[1][3]);
                }
            }
        };

        load_stage(0, 0);
        load_stage(1, 1);
        #pragma unroll 1
        for (int ki = 0; ki < 32; ki++) {
            if (ki < 31) cp_wait<1>(); else cp_wait<0>();
            __syncthreads();
            if (ki + 2 < 32) load_stage(ki + 2, (ki + 2) % 3);
            compute(ki % 3);
        }

        // bias fold
        {
            uint32_t b[2][4];
            #pragma unroll
            for (int ib = 0; ib < 2; ib++) {
                int row = wn + ib * 16 + rlo;
                ldm_x4(b[ib], Be_base + row * 48 + chi * 16);
            }
            #pragma unroll
            for (int im = 0; im < 2; im++) {
                uint32_t a[4];
                int row = wm + im * 16 + rlo;
                ldm_x4(a, Ae_base + row * 48 + chi * 16);
                mma_bf16(acc[im][0], a, b[0][0], b[0][2]);
                mma_bf16(acc[im][1], a, b[0][1], b[0][3]);
                mma_bf16(acc[im][2], a, b[1][0], b[1][2]);
                mma_bf16(acc[im][3], a, b[1][1], b[1][3]);
            }
        }

        // epilogue: divide by Z, store
        const int qr = lane >> 2;
        const int qc = (lane & 3) * 2;
        #pragma unroll
        for (int im = 0; im < 2; im++) {
            int r0g = m0 + wm + im * 16 + qr;
            float zi0 = 1.0f / *((volatile float*)&g_Z[r0g]);
            float zi1 = 1.0f / *((volatile float*)&g_Z[r0g + 8]);
            #pragma unroll
            for (int in = 0; in < 4; in++) {
                int cg = n0 + wn + in * 8 + qc;
                float* c = acc[im][in];
                float2 v0 = {c[0] * zi0, c[1] * zi0};
                float2 v1 = {c[2] * zi1, c[3] * zi1};
                *(float2*)&out[(size_t)r0g * NU + cg] = v0;
                *(float2*)&out[(size_t)(r0g + 8) * NU + cg] = v1;
            }
        }
    }
}

// ============================================================
extern "C" void kernel_launch(void* const* d_in, const int* in_sizes, int n_in,
                              void* d_out, int out_size) {
    const float* h    = (const float*)d_in[0];   // [B, F]
    const float* dom  = (const float*)d_in[1];   // [J, M, F]
    const float* W    = (const float*)d_in[2];   // [J, M, U]
    const float* bvec = (const float*)d_in[3];   // [J, U]
    float* out = (float*)d_out;                  // [B, U]

    cudaFuncSetAttribute(fused_kernel, cudaFuncAttributeMaxDynamicSharedMemorySize, 49152);

    prep_kernel<<<(BATCH + 2 * JM) / 8, 256>>>(h, dom, W);
    fused_kernel<<<NJ + 256 + 256, 256, 49152>>>(bvec, out);
}

// round 14
// speedup vs baseline: 1.9079x; 1.9079x over previous
#include <cuda_runtime.h>
#include <cuda_bf16.h>
#include <math.h>
#include <stdint.h>

#define BATCH 4096
#define FDIM  512
#define NJ    16
#define NM    64
#define NU    512
#define JM    (NJ*NM)   // 1024

// ---- scratch (device globals; no allocation allowed) ----
__device__ __nv_bfloat16 g_hb[(size_t)BATCH * FDIM];   // 4 MB
__device__ __nv_bfloat16 g_db[(size_t)JM * FDIM];      // 1 MB
__device__ __nv_bfloat16 g_Wb[(size_t)JM * NU];        // 1 MB
__device__ __nv_bfloat16 g_A2[(size_t)BATCH * JM];     // 8 MB : e-scaled Khd
__device__ float g_h2[BATCH];
__device__ float g_d2[JM];
__device__ float g_kdd[NJ];
__device__ int   g_zero;            // 1 => K_hd provably all-zero in fp32
__device__ float g_e[BATCH * NJ];
__device__ float g_Z[BATCH];

// ================= PTX helpers =================
__device__ __forceinline__ void cp16(uint32_t dst, const void* src) {
    asm volatile("cp.async.cg.shared.global [%0], [%1], 16;\n" :: "r"(dst), "l"(src));
}
__device__ __forceinline__ void cp_commit() { asm volatile("cp.async.commit_group;\n"); }
template <int N> __device__ __forceinline__ void cp_wait() {
    asm volatile("cp.async.wait_group %0;\n" :: "n"(N));
}
__device__ __forceinline__ void ldm_x4(uint32_t a[4], uint32_t addr) {
    asm volatile("ldmatrix.sync.aligned.m8n8.x4.shared.b16 {%0,%1,%2,%3}, [%4];\n"
                 : "=r"(a[0]), "=r"(a[1]), "=r"(a[2]), "=r"(a[3]) : "r"(addr));
}
__device__ __forceinline__ void ldm_x4t(uint32_t a[4], uint32_t addr) {
    asm volatile("ldmatrix.sync.aligned.m8n8.x4.trans.shared.b16 {%0,%1,%2,%3}, [%4];\n"
                 : "=r"(a[0]), "=r"(a[1]), "=r"(a[2]), "=r"(a[3]) : "r"(addr));
}
__device__ __forceinline__ void mma_bf16(float c[4], const uint32_t a[4], uint32_t b0, uint32_t b1) {
    asm volatile(
        "mma.sync.aligned.m16n8k16.row.col.f32.bf16.bf16.f32 "
        "{%0,%1,%2,%3}, {%4,%5,%6,%7}, {%8,%9}, {%0,%1,%2,%3};\n"
        : "+f"(c[0]), "+f"(c[1]), "+f"(c[2]), "+f"(c[3])
        : "r"(a[0]), "r"(a[1]), "r"(a[2]), "r"(a[3]), "r"(b0), "r"(b1));
}

// ================= stats: h2[b], d2[jm] (fp32 row sumsq), zero Z =========
__global__ void __launch_bounds__(256) stats_kernel(const float* __restrict__ h,
                                                    const float* __restrict__ dom) {
    int warp = (blockIdx.x << 3) + (threadIdx.x >> 5);
    int lane = threadIdx.x & 31;
    const float* p;
    float* o;
    if (warp < BATCH) {
        p = h + (size_t)warp * FDIM; o = &g_h2[warp];
        if (lane == 0) g_Z[warp] = 0.f;
    } else {
        int r = warp - BATCH;
        p = dom + (size_t)r * FDIM; o = &g_d2[r];
    }
    float s = 0.f;
    #pragma unroll
    for (int i = 0; i < 4; i++) {
        float4 v = *(const float4*)&p[(lane + i * 32) << 2];
        s += v.x*v.x + v.y*v.y + v.z*v.z + v.w*v.w;
    }
    #pragma unroll
    for (int off = 16; off; off >>= 1) s += __shfl_xor_sync(0xffffffffu, s, off);
    if (lane == 0) *o = s;
}

// ================= kdd via tensor cores (fp32 dom in, 32KB smem) =========
__global__ void __launch_bounds__(256) kdd_kernel(const float* __restrict__ dom) {
    extern __shared__ char smem[];           // 32 KB staging
    __shared__ float d2s[NM];
    __shared__ float ws[4];
    const int j = blockIdx.x;
    const int tid = threadIdx.x;
    const int lane = tid & 31, w = tid >> 5;
    const float* dj = dom + (size_t)j * NM * FDIM;
    uint32_t base = (uint32_t)__cvta_generic_to_shared(smem);
    const int rlo = lane & 15, chi = lane >> 4;

    float acc[8][4] = {};
    float rs[8] = {};

    #pragma unroll 1
    for (int pass = 0; pass < 2; pass++) {
        #pragma unroll
        for (int rr = 0; rr < 8; rr++) {
            int r = w * 8 + rr;
            const float* src = dj + (size_t)r * FDIM + pass * 256;
            int c = lane;
            float4 v0 = *(const float4*)&src[c * 8];
            float4 v1 = *(const float4*)&src[c * 8 + 4];
            rs[rr] += v0.x*v0.x + v0.y*v0.y + v0.z*v0.z + v0.w*v0.w
                    + v1.x*v1.x + v1.y*v1.y + v1.z*v1.z + v1.w*v1.w;
            __nv_bfloat162 p0 = __floats2bfloat162_rn(v0.x, v0.y);
            __nv_bfloat162 p1 = __floats2bfloat162_rn(v0.z, v0.w);
            __nv_bfloat162 p2 = __floats2bfloat162_rn(v1.x, v1.y);
            __nv_bfloat162 p3 = __floats2bfloat162_rn(v1.z, v1.w);
            uint4 u;
            u.x = *(uint32_t*)&p0; u.y = *(uint32_t*)&p1;
            u.z = *(uint32_t*)&p2; u.w = *(uint32_t*)&p3;
            *(uint4*)(smem + r * 512 + ((c ^ (r & 7)) << 4)) = u;
        }
        __syncthreads();
        if (w < 4) {
            #pragma unroll 4
            for (int kk = 0; kk < 16; kk++) {
                int ch = kk * 2 + chi;
                uint32_t a[4], b[4][4];
                {
                    int row = w * 16 + rlo;
                    ldm_x4(a, base + row * 512 + ((ch ^ (row & 7)) << 4));
                }
                #pragma unroll
                for (int nb = 0; nb < 4; nb++) {
                    int row = nb * 16 + rlo;
                    ldm_x4(b[nb], base + row * 512 + ((ch ^ (row & 7)) << 4));
                }
                #pragma unroll
                for (int nb = 0; nb < 4; nb++) {
                    mma_bf16(acc[2*nb],   a, b[nb][0], b[nb][2]);
                    mma_bf16(acc[2*nb+1], a, b[nb][1], b[nb][3]);
                }
            }
        }
        __syncthreads();
    }

    #pragma unroll
    for (int rr = 0; rr < 8; rr++) {
        float s = rs[rr];
        #pragma unroll
        for (int off = 16; off; off >>= 1) s += __shfl_xor_sync(0xffffffffu, s, off);
        if (lane == 0) d2s[w * 8 + rr] = s;
    }
    __syncthreads();

    if (w < 4) {
        const int qr = lane >> 2;
        const int qc = (lane & 3) * 2;
        int m0 = w * 16 + qr;
        float d2a = d2s[m0], d2b = d2s[m0 + 8];
        float s = 0.f;
        #pragma unroll
        for (int nt = 0; nt < 8; nt++) {
            int n = nt * 8 + qc;
            float d2x = d2s[n], d2y = d2s[n + 1];
            float* c = acc[nt];
            s += expf(-2.f * (d2a + d2x - 2.f * c[0]));
            s += expf(-2.f * (d2a + d2y - 2.f * c[1]));
            s += expf(-2.f * (d2b + d2x - 2.f * c[2]));
            s += expf(-2.f * (d2b + d2y - 2.f * c[3]));
        }
        #pragma unroll
        for (int off = 16; off; off >>= 1) s += __shfl_xor_sync(0xffffffffu, s, off);
        if (lane == 0) ws[w] = s;
    }
    __syncthreads();
    if (tid == 0) g_kdd[j] = (ws[0] + ws[1] + ws[2] + ws[3]) * (1.0f / (NM * NM));
}

// ================= decide: g_zero = (sqrt(h2min)-sqrt(d2max))^2 >= 60 ====
// Cauchy-Schwarz: sqdist >= (sqrt(h2)-sqrt(d2))^2, so exponent <= -120
// => fp32 exp underflows to exactly 0 for every (b, jm) pair.
__global__ void __launch_bounds__(256) decide_kernel() {
    __shared__ float mn[8], mx[8];
    int tid = threadIdx.x;
    float h2min = 3.4e38f;
    for (int i = tid; i < BATCH; i += 256) h2min = fminf(h2min, g_h2[i]);
    float d2max = 0.f;
    for (int i = tid; i < JM; i += 256) d2max = fmaxf(d2max, g_d2[i]);
    #pragma unroll
    for (int off = 16; off; off >>= 1) {
        h2min = fminf(h2min, __shfl_xor_sync(0xffffffffu, h2min, off));
        d2max = fmaxf(d2max, __shfl_xor_sync(0xffffffffu, d2max, off));
    }
    if ((tid & 31) == 0) { mn[tid >> 5] = h2min; mx[tid >> 5] = d2max; }
    __syncthreads();
    if (tid == 0) {
        float a = 3.4e38f, b = 0.f;
        #pragma unroll
        for (int i = 0; i < 8; i++) { a = fminf(a, mn[i]); b = fmaxf(b, mx[i]); }
        float diff = sqrtf(a) - sqrtf(b);
        g_zero = (diff > 0.f && diff * diff >= 60.f) ? 1 : 0;
    }
}

// ================= bias path: out[b,:] = sum_j prob_j * bvec[j,:] ========
__global__ void __launch_bounds__(256) bias_kernel(const float* __restrict__ bvec,
                                                   float* __restrict__ out) {
    if (!g_zero) return;
    __shared__ float es[NJ];
    int tid = threadIdx.x;
    if (tid < NJ) es[tid] = expf(-1.0f - g_kdd[tid]);
    __syncthreads();
    float Z = 0.f;
    #pragma unroll
    for (int j = 0; j < NJ; j++) Z += es[j];
    float inv = 1.0f / Z;
    int u0 = tid * 2;
    float cx = 0.f, cy = 0.f;
    #pragma unroll
    for (int j = 0; j < NJ; j++) {
        float p = es[j] * inv;
        float2 bv = *(const float2*)&bvec[(size_t)j * NU + u0];
        cx += p * bv.x;
        cy += p * bv.y;
    }
    float2 o = {cx, cy};
    int r0 = blockIdx.x * 16;
    #pragma unroll
    for (int r = 0; r < 16; r++)
        *(float2*)&out[(size_t)(r0 + r) * NU + u0] = o;
}

// ================= convert (fallback only): fp32 -> bf16 ================
__global__ void __launch_bounds__(256) convert_kernel(const float* __restrict__ h,
                                                      const float* __restrict__ dom,
                                                      const float* __restrict__ W) {
    if (g_zero) return;
    int warp = (blockIdx.x << 3) + (threadIdx.x >> 5);
    int lane = threadIdx.x & 31;
    const float* p;
    __nv_bfloat16* dst;
    if (warp < BATCH) {
        p = h + (size_t)warp * FDIM; dst = g_hb + (size_t)warp * FDIM;
    } else if (warp < BATCH + JM) {
        int r = warp - BATCH;
        p = dom + (size_t)r * FDIM; dst = g_db + (size_t)r * FDIM;
    } else {
        int r = warp - BATCH - JM;
        p = W + (size_t)r * NU; dst = g_Wb + (size_t)r * NU;
    }
    #pragma unroll
    for (int i = 0; i < 4; i++) {
        int idx = (lane + i * 32) << 2;
        float4 v = *(const float4*)&p[idx];
        __nv_bfloat162 o0 = __floats2bfloat162_rn(v.x, v.y);
        __nv_bfloat162 o1 = __floats2bfloat162_rn(v.z, v.w);
        uint2 u; u.x = *(uint32_t*)&o0; u.y = *(uint32_t*)&o1;
        *(uint2*)&dst[idx] = u;
    }
}

// ================= GEMM1 (fallback): A2 = e * exp(...) ===================
// 128x128 tile (=2 full domains), BK=32, 3-stage, 256 thr, 2 CTAs/SM.
__global__ void __launch_bounds__(256, 2) gemm1_kernel() {
    if (g_zero) return;
    extern __shared__ char smem[];
    __shared__ float jp[128][2];
    __shared__ float es[128][2];
    __shared__ float kddm[2];
    const int tid = threadIdx.x;
    const int lane = tid & 31, wid = tid >> 5;
    const int wm = (wid >> 2) * 64;
    const int wn = (wid & 3) * 32;
    const int m0 = blockIdx.y * 128;
    const int n0 = blockIdx.x * 128;
    const int j0 = blockIdx.x * 2;

    uint32_t base = (uint32_t)__cvta_generic_to_shared(smem);

    if (tid < 256) { jp[tid >> 1][tid & 1] = 0.f; }
    if (tid < 2) kddm[tid] = g_kdd[j0 + tid];

    const int rlo = lane & 15, chi = lane >> 4;
    int arow[4], asw[4], brow[2], bsw[2];
    #pragma unroll
    for (int im = 0; im < 4; im++) { arow[im] = wm + im * 16 + rlo; asw[im] = (arow[im] >> 1) & 3; }
    #pragma unroll
    for (int ib = 0; ib < 2; ib++) { brow[ib] = wn + ib * 16 + rlo; bsw[ib] = (brow[ib] >> 1) & 3; }

    float acc[4][4][4] = {};

    auto load_stage = [&](int ki, int s) {
        const __nv_bfloat16* ha = g_hb + (size_t)m0 * FDIM + ki * 32;
        const __nv_bfloat16* da = g_db + (size_t)n0 * FDIM + ki * 32;
        uint32_t a_s = base + s * 16384;
        uint32_t b_s = a_s + 8192;
        #pragma unroll
        for (int i = 0; i < 2; i++) {
            int lin = tid + i * 256;
            int r = lin >> 2, c = lin & 3;
            uint32_t off = (uint32_t)(r * 64 + (((c ^ ((r >> 1) & 3))) << 4));
            cp16(a_s + off, ha + (size_t)r * FDIM + c * 8);
            cp16(b_s + off, da + (size_t)r * FDIM + c * 8);
        }
        cp_commit();
    };

    auto compute = [&](int s) {
        uint32_t a_s = base + s * 16384;
        uint32_t b_s = a_s + 8192;
        #pragma unroll
        for (int kk = 0; kk < 2; kk++) {
            int ch = kk * 2 + chi;
            uint32_t a[4][4], b[2][4];
            #pragma unroll
            for (int im = 0; im < 4; im++)
                ldm_x4(a[im], a_s + arow[im] * 64 + ((ch ^ asw[im]) << 4));
            #pragma unroll
            for (int ib = 0; ib < 2; ib++)
                ldm_x4(b[ib], b_s + brow[ib] * 64 + ((ch ^ bsw[ib]) << 4));
            #pragma unroll
            for (int im = 0; im < 4; im++) {
                mma_bf16(acc[im][0], a[im], b[0][0], b[0][2]);
                mma_bf16(acc[im][1], a[im], b[0][1], b[0][3]);
                mma_bf16(acc[im][2], a[im], b[1][0], b[1][2]);
                mma_bf16(acc[im][3], a[im], b[1][1], b[1][3]);
            }
        }
    };

    load_stage(0, 0);
    load_stage(1, 1);
    #pragma unroll 1
    for (int ki = 0; ki < 16; ki++) {
        if (ki < 15) cp_wait<1>(); else cp_wait<0>();
        __syncthreads();
        if (ki + 2 < 16) load_stage(ki + 2, (ki + 2) % 3);
        compute(ki % 3);
    }

    const int qr = lane >> 2;
    const int qc = (lane & 3) * 2;
    const int jj = wn >> 6;
    #pragma unroll
    for (int im = 0; im < 4; im++) {
        int r0g = m0 + wm + im * 16 + qr;
        float h2a = g_h2[r0g], h2b = g_h2[r0g + 8];
        float rs0 = 0.f, rs1 = 0.f;
        #pragma unroll
        for (int in = 0; in < 4; in++) {
            int cg = n0 + wn + in * 8 + qc;
            float d2x = g_d2[cg], d2y = g_d2[cg + 1];
            float* c = acc[im][in];
            c[0] = expf(4.f * c[0] - 2.f * (h2a + d2x));
            c[1] = expf(4.f * c[1] - 2.f * (h2a + d2y));
            c[2] = expf(4.f * c[2] - 2.f * (h2b + d2x));
            c[3] = expf(4.f * c[3] - 2.f * (h2b + d2y));
            rs0 += c[0] + c[1];
            rs1 += c[2] + c[3];
        }
        rs0 += __shfl_xor_sync(0xffffffffu, rs0, 1);
        rs0 += __shfl_xor_sync(0xffffffffu, rs0, 2);
        rs1 += __shfl_xor_sync(0xffffffffu, rs1, 1);
        rs1 += __shfl_xor_sync(0xffffffffu, rs1, 2);
        if ((lane & 3) == 0) {
            atomicAdd(&jp[wm + im * 16 + qr][jj], rs0);
            atomicAdd(&jp[wm + im * 16 + qr + 8][jj], rs1);
        }
    }
    __syncthreads();
    if (tid < 256) {
        int rl = tid >> 1, j = tid & 1;
        float jsum = jp[rl][j];
        float e = expf(jsum * (1.0f / 32.0f) - 1.0f - kddm[j]);
        es[rl][j] = e;
        g_e[(m0 + rl) * NJ + j0 + j] = e;
        atomicAdd(&g_Z[m0 + rl], e);
    }
    __syncthreads();
    #pragma unroll
    for (int im = 0; im < 4; im++) {
        int rl = wm + im * 16 + qr;
        int r0g = m0 + rl;
        float e0 = es[rl][jj], e1 = es[rl + 8][jj];
        #pragma unroll
        for (int in = 0; in < 4; in++) {
            int cg = n0 + wn + in * 8 + qc;
            float* c = acc[im][in];
            *(__nv_bfloat162*)&g_A2[(size_t)r0g * JM + cg] =
                __floats2bfloat162_rn(c[0] * e0, c[1] * e0);
            *(__nv_bfloat162*)&g_A2[(size_t)(r0g + 8) * JM + cg] =
                __floats2bfloat162_rn(c[2] * e1, c[3] * e1);
        }
    }
}

// ================= GEMM2 (fallback): out = (A2 @ W + e @ bvec) / Z =======
// 128x64 tile, BK=64, 3-stage, 256 threads, frag double-buffered.
__global__ void __launch_bounds__(256, 2) gemm2_kernel(const float* __restrict__ bvec,
                                                       float* __restrict__ out) {
    if (g_zero) return;
    extern __shared__ char smem[];
    const int tid = threadIdx.x;
    const int lane = tid & 31, wid = tid >> 5;
    const int wm = (wid >> 1) * 32;
    const int wn = (wid & 1) * 32;
    const int m0 = blockIdx.y * 128;
    const int n0 = blockIdx.x * 64;

    uint32_t base = (uint32_t)__cvta_generic_to_shared(smem);
    uint32_t Bs_base = base + 49152;
    uint32_t Ae_base = base + 73728;
    uint32_t Be_base = base + 79872;
    __nv_bfloat16* Ae = (__nv_bfloat16*)(smem + 73728);
    __nv_bfloat16* Be = (__nv_bfloat16*)(smem + 79872);

    for (int idx = tid; idx < 128 * 16; idx += 256) {
        int rr = idx >> 4, j = idx & 15;
        Ae[rr * 24 + j] = __float2bfloat16(g_e[(size_t)(m0 + rr) * NJ + j]);
        if (rr < 64) Be[rr * 24 + j] = __float2bfloat16(bvec[(size_t)j * NU + n0 + rr]);
    }

    const int rlo = lane & 15, chi = lane >> 4;
    int arow[2], asw[2];
    #pragma unroll
    for (int im = 0; im < 2; im++) { arow[im] = wm + im * 16 + rlo; asw[im] = arow[im] & 7; }

    float acc[2][4][4] = {};

    auto load_stage = [&](int ki, int s) {
        const __nv_bfloat16* asrc = g_A2 + (size_t)m0 * JM + ki * 64;
        const __nv_bfloat16* bsrc = g_Wb + (size_t)ki * 64 * NU + n0;
        uint32_t a_s = base + s * 16384;
        uint32_t b_s = Bs_base + s * 8192;
        #pragma unroll
        for (int i = 0; i < 4; i++) {
            int lin = tid + i * 256;
            int r = lin >> 3, c = lin & 7;
            cp16(a_s + r * 128 + ((c ^ (r & 7)) << 4), asrc + (size_t)r * JM + c * 8);
        }
        #pragma unroll
        for (int i = 0; i < 2; i++) {
            int lin = tid + i * 256;
            int r = lin >> 3, c = lin & 7;
            cp16(b_s + r * 128 + ((c ^ (r & 7)) << 4), bsrc + (size_t)r * NU + c * 8);
        }
        cp_commit();
    };

    uint32_t fa[2][2][4], fb[2][2][4];
    auto ldfrag = [&](uint32_t a_s, uint32_t b_s, int kk, int buf) {
        int ch = kk * 2 + chi;
        #pragma unroll
        for (int im = 0; im < 2; im++)
            ldm_x4(fa[buf][im], a_s + arow[im] * 128 + ((ch ^ asw[im]) << 4));
        #pragma unroll
        for (int ib = 0; ib < 2; ib++) {
            int row = kk * 16 + rlo;
            int cb = (wn >> 3) + ib * 2 + chi;
            ldm_x4t(fb[buf][ib], b_s + row * 128 + ((cb ^ (row & 7)) << 4));
        }
    };
    auto domma = [&](int buf) {
        #pragma unroll
        for (int im = 0; im < 2; im++) {
            mma_bf16(acc[im][0], fa[buf][im], fb[buf][0][0], fb[buf][0][1]);
            mma_bf16(acc[im][1], fa[buf][im], fb[buf][0][2], fb[buf][0][3]);
            mma_bf16(acc[im][2], fa[buf][im], fb[buf][1][0], fb[buf][1][1]);
            mma_bf16(acc[im][3], fa[buf][im], fb[buf][1][2], fb[buf][1][3]);
        }
    };
    auto compute = [&](int s) {
        uint32_t a_s = base + s * 16384;
        uint32_t b_s = Bs_base + s * 8192;
        ldfrag(a_s, b_s, 0, 0);
        #pragma unroll
        for (int kk = 0; kk < 4; kk++) {
            if (kk < 3) ldfrag(a_s, b_s, kk + 1, (kk + 1) & 1);
            domma(kk & 1);
        }
    };

    load_stage(0, 0);
    load_stage(1, 1);
    #pragma unroll 1
    for (int ki = 0; ki < 16; ki++) {
        if (ki < 15) cp_wait<1>(); else cp_wait<0>();
        __syncthreads();
        if (ki + 2 < 16) load_stage(ki + 2, (ki + 2) % 3);
        compute(ki % 3);
    }

    {
        uint32_t b[2][4];
        #pragma unroll
        for (int ib = 0; ib < 2; ib++) {
            int row = wn + ib * 16 + rlo;
            ldm_x4(b[ib], Be_base + row * 48 + chi * 16);
        }
        #pragma unroll
        for (int im = 0; im < 2; im++) {
            uint32_t a[4];
            int row = wm + im * 16 + rlo;
            ldm_x4(a, Ae_base + row * 48 + chi * 16);
            mma_bf16(acc[im][0], a, b[0][0], b[0][2]);
            mma_bf16(acc[im][1], a, b[0][1], b[0][3]);
            mma_bf16(acc[im][2], a, b[1][0], b[1][2]);
            mma_bf16(acc[im][3], a, b[1][1], b[1][3]);
        }
    }

    const int qr = lane >> 2;
    const int qc = (lane & 3) * 2;
    #pragma unroll
    for (int im = 0; im < 2; im++) {
        int r0g = m0 + wm + im * 16 + qr;
        float zi0 = 1.0f / g_Z[r0g];
        float zi1 = 1.0f / g_Z[r0g + 8];
        #pragma unroll
        for (int in = 0; in < 4; in++) {
            int cg = n0 + wn + in * 8 + qc;
            float* c = acc[im][in];
            float2 v0 = {c[0] * zi0, c[1] * zi0};
            float2 v1 = {c[2] * zi1, c[3] * zi1};
            *(float2*)&out[(size_t)r0g * NU + cg] = v0;
            *(float2*)&out[(size_t)(r0g + 8) * NU + cg] = v1;
        }
    }
}

// ============================================================
extern "C" void kernel_launch(void* const* d_in, const int* in_sizes, int n_in,
                              void* d_out, int out_size) {
    const float* h    = (const float*)d_in[0];   // [B, F]
    const float* dom  = (const float*)d_in[1];   // [J, M, F]
    const float* W    = (const float*)d_in[2];   // [J, M, U]
    const float* bvec = (const float*)d_in[3];   // [J, U]
    float* out = (float*)d_out;                  // [B, U]

    cudaFuncSetAttribute(kdd_kernel,   cudaFuncAttributeMaxDynamicSharedMemorySize, 32768);
    cudaFuncSetAttribute(gemm1_kernel, cudaFuncAttributeMaxDynamicSharedMemorySize, 49152);
    cudaFuncSetAttribute(gemm2_kernel, cudaFuncAttributeMaxDynamicSharedMemorySize, 82944);

    stats_kernel<<<(BATCH + JM) / 8, 256>>>(h, dom);
    kdd_kernel<<<NJ, 256, 32768>>>(dom);
    decide_kernel<<<1, 256>>>();
    // zero path (taken when K_hd provably underflows to 0 in fp32):
    bias_kernel<<<BATCH / 16, 256>>>(bvec, out);
    // fallback path (no-ops when g_zero == 1):
    convert_kernel<<<(BATCH + 2 * JM) / 8, 256>>>(h, dom, W);
    gemm1_kernel<<<dim3(JM / 128, BATCH / 128), 256, 49152>>>();
    gemm2_kernel<<<dim3(NU / 64, BATCH / 128), 256, 82944>>>(bvec, out);
}

// round 15
// speedup vs baseline: 2.2444x; 1.1764x over previous
#include <cuda_runtime.h>
#include <cuda_bf16.h>
#include <math.h>
#include <stdint.h>

#define BATCH 4096
#define FDIM  512
#define NJ    16
#define NM    64
#define NU    512
#define JM    (NJ*NM)   // 1024

// ---- scratch (device globals; no allocation allowed) ----
__device__ __nv_bfloat16 g_hb[(size_t)BATCH * FDIM];   // 4 MB
__device__ __nv_bfloat16 g_db[(size_t)JM * FDIM];      // 1 MB
__device__ __nv_bfloat16 g_Wb[(size_t)JM * NU];        // 1 MB
__device__ __nv_bfloat16 g_A2[(size_t)BATCH * JM];     // 8 MB : e-scaled Khd
__device__ float g_h2[BATCH];
__device__ float g_d2[JM];
__device__ float g_kdd[NJ];
__device__ int   g_zero;            // 1 => K_hd provably all-zero in fp32
__device__ int   g_cnt = 0;         // stats completion counter
__device__ float g_e[BATCH * NJ];
__device__ float g_Z[BATCH];

// ================= PTX helpers =================
__device__ __forceinline__ void cp16(uint32_t dst, const void* src) {
    asm volatile("cp.async.cg.shared.global [%0], [%1], 16;\n" :: "r"(dst), "l"(src));
}
__device__ __forceinline__ void cp_commit() { asm volatile("cp.async.commit_group;\n"); }
template <int N> __device__ __forceinline__ void cp_wait() {
    asm volatile("cp.async.wait_group %0;\n" :: "n"(N));
}
__device__ __forceinline__ void ldm_x4(uint32_t a[4], uint32_t addr) {
    asm volatile("ldmatrix.sync.aligned.m8n8.x4.shared.b16 {%0,%1,%2,%3}, [%4];\n"
                 : "=r"(a[0]), "=r"(a[1]), "=r"(a[2]), "=r"(a[3]) : "r"(addr));
}
__device__ __forceinline__ void ldm_x4t(uint32_t a[4], uint32_t addr) {
    asm volatile("ldmatrix.sync.aligned.m8n8.x4.trans.shared.b16 {%0,%1,%2,%3}, [%4];\n"
                 : "=r"(a[0]), "=r"(a[1]), "=r"(a[2]), "=r"(a[3]) : "r"(addr));
}
__device__ __forceinline__ void mma_bf16(float c[4], const uint32_t a[4], uint32_t b0, uint32_t b1) {
    asm volatile(
        "mma.sync.aligned.m16n8k16.row.col.f32.bf16.bf16.f32 "
        "{%0,%1,%2,%3}, {%4,%5,%6,%7}, {%8,%9}, {%0,%1,%2,%3};\n"
        : "+f"(c[0]), "+f"(c[1]), "+f"(c[2]), "+f"(c[3])
        : "r"(a[0]), "r"(a[1]), "r"(a[2]), "r"(a[3]), "r"(b0), "r"(b1));
}

// ====== front kernel: [0,16)=kdd, [16,656)=stats, 656=decide =============
// kdd: self-contained (reads fp32 dom, computes own d2 in-block).
// stats: h2[b] / d2[jm] row sumsq, zero Z, bump g_cnt.
// decide: spin for all 640 stats blocks, then Cauchy-Schwarz underflow test:
//   sqdist >= (sqrt(h2)-sqrt(d2))^2; if >= 60 for ALL pairs, exponent <= -120
//   => fp32 exp == 0 everywhere => bias-only path is exact.
__global__ void __launch_bounds__(256) front_kernel(const float* __restrict__ h,
                                                    const float* __restrict__ dom) {
    extern __shared__ char smem[];           // 32 KB (kdd blocks only)
    __shared__ float d2s[NM];
    __shared__ float ws[8];
    const int bid = blockIdx.x;
    const int tid = threadIdx.x;
    const int lane = tid & 31, w = tid >> 5;

    if (bid < NJ) {
        // ---------------- kdd block ----------------
        const int j = bid;
        const float* dj = dom + (size_t)j * NM * FDIM;
        uint32_t base = (uint32_t)__cvta_generic_to_shared(smem);
        const int rlo = lane & 15, chi = lane >> 4;
        float acc[8][4] = {};
        float rs[8] = {};
        #pragma unroll 1
        for (int pass = 0; pass < 2; pass++) {
            #pragma unroll
            for (int rr = 0; rr < 8; rr++) {
                int r = w * 8 + rr;
                const float* src = dj + (size_t)r * FDIM + pass * 256;
                int c = lane;
                float4 v0 = *(const float4*)&src[c * 8];
                float4 v1 = *(const float4*)&src[c * 8 + 4];
                rs[rr] += v0.x*v0.x + v0.y*v0.y + v0.z*v0.z + v0.w*v0.w
                        + v1.x*v1.x + v1.y*v1.y + v1.z*v1.z + v1.w*v1.w;
                __nv_bfloat162 p0 = __floats2bfloat162_rn(v0.x, v0.y);
                __nv_bfloat162 p1 = __floats2bfloat162_rn(v0.z, v0.w);
                __nv_bfloat162 p2 = __floats2bfloat162_rn(v1.x, v1.y);
                __nv_bfloat162 p3 = __floats2bfloat162_rn(v1.z, v1.w);
                uint4 u;
                u.x = *(uint32_t*)&p0; u.y = *(uint32_t*)&p1;
                u.z = *(uint32_t*)&p2; u.w = *(uint32_t*)&p3;
                *(uint4*)(smem + r * 512 + ((c ^ (r & 7)) << 4)) = u;
            }
            __syncthreads();
            if (w < 4) {
                #pragma unroll 4
                for (int kk = 0; kk < 16; kk++) {
                    int ch = kk * 2 + chi;
                    uint32_t a[4], b[4][4];
                    {
                        int row = w * 16 + rlo;
                        ldm_x4(a, base + row * 512 + ((ch ^ (row & 7)) << 4));
                    }
                    #pragma unroll
                    for (int nb = 0; nb < 4; nb++) {
                        int row = nb * 16 + rlo;
                        ldm_x4(b[nb], base + row * 512 + ((ch ^ (row & 7)) << 4));
                    }
                    #pragma unroll
                    for (int nb = 0; nb < 4; nb++) {
                        mma_bf16(acc[2*nb],   a, b[nb][0], b[nb][2]);
                        mma_bf16(acc[2*nb+1], a, b[nb][1], b[nb][3]);
                    }
                }
            }
            __syncthreads();
        }
        #pragma unroll
        for (int rr = 0; rr < 8; rr++) {
            float s = rs[rr];
            #pragma unroll
            for (int off = 16; off; off >>= 1) s += __shfl_xor_sync(0xffffffffu, s, off);
            if (lane == 0) d2s[w * 8 + rr] = s;
        }
        __syncthreads();
        if (w < 4) {
            const int qr = lane >> 2;
            const int qc = (lane & 3) * 2;
            int m0 = w * 16 + qr;
            float d2a = d2s[m0], d2b = d2s[m0 + 8];
            float s = 0.f;
            #pragma unroll
            for (int nt = 0; nt < 8; nt++) {
                int n = nt * 8 + qc;
                float d2x = d2s[n], d2y = d2s[n + 1];
                float* c = acc[nt];
                s += expf(-2.f * (d2a + d2x - 2.f * c[0]));
                s += expf(-2.f * (d2a + d2y - 2.f * c[1]));
                s += expf(-2.f * (d2b + d2x - 2.f * c[2]));
                s += expf(-2.f * (d2b + d2y - 2.f * c[3]));
            }
            #pragma unroll
            for (int off = 16; off; off >>= 1) s += __shfl_xor_sync(0xffffffffu, s, off);
            if (lane == 0) ws[w] = s;
        }
        __syncthreads();
        if (tid == 0) g_kdd[j] = (ws[0] + ws[1] + ws[2] + ws[3]) * (1.0f / (NM * NM));
        return;
    }

    if (bid < NJ + 640) {
        // ---------------- stats block: 8 rows of h/dom ----------------
        int warp = (bid - NJ) * 8 + w;
        const float* p;
        float* o;
        if (warp < BATCH) {
            p = h + (size_t)warp * FDIM; o = &g_h2[warp];
            if (lane == 0) g_Z[warp] = 0.f;
        } else {
            int r = warp - BATCH;
            p = dom + (size_t)r * FDIM; o = &g_d2[r];
        }
        float s = 0.f;
        #pragma unroll
        for (int i = 0; i < 4; i++) {
            float4 v = *(const float4*)&p[(lane + i * 32) << 2];
            s += v.x*v.x + v.y*v.y + v.z*v.z + v.w*v.w;
        }
        #pragma unroll
        for (int off = 16; off; off >>= 1) s += __shfl_xor_sync(0xffffffffu, s, off);
        if (lane == 0) *o = s;
        __syncthreads();
        if (tid == 0) {
            __threadfence();
            atomicAdd(&g_cnt, 1);
        }
        return;
    }

    // ---------------- decide block ----------------
    {
        __shared__ float mn[8], mx[8];
        if (tid == 0) {
            while (atomicAdd(&g_cnt, 0) < 640) { }
            atomicExch(&g_cnt, 0);     // reset for next graph replay
        }
        __syncthreads();
        __threadfence();
        float h2min = 3.4e38f;
        for (int i = tid; i < BATCH; i += 256) h2min = fminf(h2min, g_h2[i]);
        float d2max = 0.f;
        for (int i = tid; i < JM; i += 256) d2max = fmaxf(d2max, g_d2[i]);
        #pragma unroll
        for (int off = 16; off; off >>= 1) {
            h2min = fminf(h2min, __shfl_xor_sync(0xffffffffu, h2min, off));
            d2max = fmaxf(d2max, __shfl_xor_sync(0xffffffffu, d2max, off));
        }
        if (lane == 0) { mn[w] = h2min; mx[w] = d2max; }
        __syncthreads();
        if (tid == 0) {
            float a = 3.4e38f, b = 0.f;
            #pragma unroll
            for (int i = 0; i < 8; i++) { a = fminf(a, mn[i]); b = fmaxf(b, mx[i]); }
            float diff = sqrtf(a) - sqrtf(b);
            g_zero = (diff > 0.f && diff * diff >= 60.f) ? 1 : 0;
        }
    }
}

// ================= bias path: out[b,:] = sum_j prob_j * bvec[j,:] ========
// grid = BATCH/4, 4 rows per block
__global__ void __launch_bounds__(256) bias_kernel(const float* __restrict__ bvec,
                                                   float* __restrict__ out) {
    if (!g_zero) return;
    __shared__ float es[NJ];
    int tid = threadIdx.x;
    if (tid < NJ) es[tid] = expf(-1.0f - g_kdd[tid]);
    __syncthreads();
    float Z = 0.f;
    #pragma unroll
    for (int j = 0; j < NJ; j++) Z += es[j];
    float inv = 1.0f / Z;
    int u0 = tid * 2;
    float cx = 0.f, cy = 0.f;
    #pragma unroll
    for (int j = 0; j < NJ; j++) {
        float p = es[j] * inv;
        float2 bv = *(const float2*)&bvec[(size_t)j * NU + u0];
        cx += p * bv.x;
        cy += p * bv.y;
    }
    float2 o = {cx, cy};
    int r0 = blockIdx.x * 4;
    #pragma unroll
    for (int r = 0; r < 4; r++)
        *(float2*)&out[(size_t)(r0 + r) * NU + u0] = o;
}

// ================= convert (fallback only): fp32 -> bf16 ================
__global__ void __launch_bounds__(256) convert_kernel(const float* __restrict__ h,
                                                      const float* __restrict__ dom,
                                                      const float* __restrict__ W) {
    if (g_zero) return;
    int warp = (blockIdx.x << 3) + (threadIdx.x >> 5);
    int lane = threadIdx.x & 31;
    const float* p;
    __nv_bfloat16* dst;
    if (warp < BATCH) {
        p = h + (size_t)warp * FDIM; dst = g_hb + (size_t)warp * FDIM;
    } else if (warp < BATCH + JM) {
        int r = warp - BATCH;
        p = dom + (size_t)r * FDIM; dst = g_db + (size_t)r * FDIM;
    } else {
        int r = warp - BATCH - JM;
        p = W + (size_t)r * NU; dst = g_Wb + (size_t)r * NU;
    }
    #pragma unroll
    for (int i = 0; i < 4; i++) {
        int idx = (lane + i * 32) << 2;
        float4 v = *(const float4*)&p[idx];
        __nv_bfloat162 o0 = __floats2bfloat162_rn(v.x, v.y);
        __nv_bfloat162 o1 = __floats2bfloat162_rn(v.z, v.w);
        uint2 u; u.x = *(uint32_t*)&o0; u.y = *(uint32_t*)&o1;
        *(uint2*)&dst[idx] = u;
    }
}

// ================= GEMM1 (fallback): A2 = e * exp(...) ===================
__global__ void __launch_bounds__(256, 2) gemm1_kernel() {
    if (g_zero) return;
    extern __shared__ char smem[];
    __shared__ float jp[128][2];
    __shared__ float es[128][2];
    __shared__ float kddm[2];
    const int tid = threadIdx.x;
    const int lane = tid & 31, wid = tid >> 5;
    const int wm = (wid >> 2) * 64;
    const int wn = (wid & 3) * 32;
    const int m0 = blockIdx.y * 128;
    const int n0 = blockIdx.x * 128;
    const int j0 = blockIdx.x * 2;

    uint32_t base = (uint32_t)__cvta_generic_to_shared(smem);

    if (tid < 256) { jp[tid >> 1][tid & 1] = 0.f; }
    if (tid < 2) kddm[tid] = g_kdd[j0 + tid];

    const int rlo = lane & 15, chi = lane >> 4;
    int arow[4], asw[4], brow[2], bsw[2];
    #pragma unroll
    for (int im = 0; im < 4; im++) { arow[im] = wm + im * 16 + rlo; asw[im] = (arow[im] >> 1) & 3; }
    #pragma unroll
    for (int ib = 0; ib < 2; ib++) { brow[ib] = wn + ib * 16 + rlo; bsw[ib] = (brow[ib] >> 1) & 3; }

    float acc[4][4][4] = {};

    auto load_stage = [&](int ki, int s) {
        const __nv_bfloat16* ha = g_hb + (size_t)m0 * FDIM + ki * 32;
        const __nv_bfloat16* da = g_db + (size_t)n0 * FDIM + ki * 32;
        uint32_t a_s = base + s * 16384;
        uint32_t b_s = a_s + 8192;
        #pragma unroll
        for (int i = 0; i < 2; i++) {
            int lin = tid + i * 256;
            int r = lin >> 2, c = lin & 3;
            uint32_t off = (uint32_t)(r * 64 + (((c ^ ((r >> 1) & 3))) << 4));
            cp16(a_s + off, ha + (size_t)r * FDIM + c * 8);
            cp16(b_s + off, da + (size_t)r * FDIM + c * 8);
        }
        cp_commit();
    };

    auto compute = [&](int s) {
        uint32_t a_s = base + s * 16384;
        uint32_t b_s = a_s + 8192;
        #pragma unroll
        for (int kk = 0; kk < 2; kk++) {
            int ch = kk * 2 + chi;
            uint32_t a[4][4], b[2][4];
            #pragma unroll
            for (int im = 0; im < 4; im++)
                ldm_x4(a[im], a_s + arow[im] * 64 + ((ch ^ asw[im]) << 4));
            #pragma unroll
            for (int ib = 0; ib < 2; ib++)
                ldm_x4(b[ib], b_s + brow[ib] * 64 + ((ch ^ bsw[ib]) << 4));
            #pragma unroll
            for (int im = 0; im < 4; im++) {
                mma_bf16(acc[im][0], a[im], b[0][0], b[0][2]);
                mma_bf16(acc[im][1], a[im], b[0][1], b[0][3]);
                mma_bf16(acc[im][2], a[im], b[1][0], b[1][2]);
                mma_bf16(acc[im][3], a[im], b[1][1], b[1][3]);
            }
        }
    };

    load_stage(0, 0);
    load_stage(1, 1);
    #pragma unroll 1
    for (int ki = 0; ki < 16; ki++) {
        if (ki < 15) cp_wait<1>(); else cp_wait<0>();
        __syncthreads();
        if (ki + 2 < 16) load_stage(ki + 2, (ki + 2) % 3);
        compute(ki % 3);
    }

    const int qr = lane >> 2;
    const int qc = (lane & 3) * 2;
    const int jj = wn >> 6;
    #pragma unroll
    for (int im = 0; im < 4; im++) {
        int r0g = m0 + wm + im * 16 + qr;
        float h2a = g_h2[r0g], h2b = g_h2[r0g + 8];
        float rs0 = 0.f, rs1 = 0.f;
        #pragma unroll
        for (int in = 0; in < 4; in++) {
            int cg = n0 + wn + in * 8 + qc;
            float d2x = g_d2[cg], d2y = g_d2[cg + 1];
            float* c = acc[im][in];
            c[0] = expf(4.f * c[0] - 2.f * (h2a + d2x));
            c[1] = expf(4.f * c[1] - 2.f * (h2a + d2y));
            c[2] = expf(4.f * c[2] - 2.f * (h2b + d2x));
            c[3] = expf(4.f * c[3] - 2.f * (h2b + d2y));
            rs0 += c[0] + c[1];
            rs1 += c[2] + c[3];
        }
        rs0 += __shfl_xor_sync(0xffffffffu, rs0, 1);
        rs0 += __shfl_xor_sync(0xffffffffu, rs0, 2);
        rs1 += __shfl_xor_sync(0xffffffffu, rs1, 1);
        rs1 += __shfl_xor_sync(0xffffffffu, rs1, 2);
        if ((lane & 3) == 0) {
            atomicAdd(&jp[wm + im * 16 + qr][jj], rs0);
            atomicAdd(&jp[wm + im * 16 + qr + 8][jj], rs1);
        }
    }
    __syncthreads();
    if (tid < 256) {
        int rl = tid >> 1, j = tid & 1;
        float jsum = jp[rl][j];
        float e = expf(jsum * (1.0f / 32.0f) - 1.0f - kddm[j]);
        es[rl][j] = e;
        g_e[(m0 + rl) * NJ + j0 + j] = e;
        atomicAdd(&g_Z[m0 + rl], e);
    }
    __syncthreads();
    #pragma unroll
    for (int im = 0; im < 4; im++) {
        int rl = wm + im * 16 + qr;
        int r0g = m0 + rl;
        float e0 = es[rl][jj], e1 = es[rl + 8][jj];
        #pragma unroll
        for (int in = 0; in < 4; in++) {
            int cg = n0 + wn + in * 8 + qc;
            float* c = acc[im][in];
            *(__nv_bfloat162*)&g_A2[(size_t)r0g * JM + cg] =
                __floats2bfloat162_rn(c[0] * e0, c[1] * e0);
            *(__nv_bfloat162*)&g_A2[(size_t)(r0g + 8) * JM + cg] =
                __floats2bfloat162_rn(c[2] * e1, c[3] * e1);
        }
    }
}

// ================= GEMM2 (fallback): out = (A2 @ W + e @ bvec) / Z =======
__global__ void __launch_bounds__(256, 2) gemm2_kernel(const float* __restrict__ bvec,
                                                       float* __restrict__ out) {
    if (g_zero) return;
    extern __shared__ char smem[];
    const int tid = threadIdx.x;
    const int lane = tid & 31, wid = tid >> 5;
    const int wm = (wid >> 1) * 32;
    const int wn = (wid & 1) * 32;
    const int m0 = blockIdx.y * 128;
    const int n0 = blockIdx.x * 64;

    uint32_t base = (uint32_t)__cvta_generic_to_shared(smem);
    uint32_t Bs_base = base + 49152;
    uint32_t Ae_base = base + 73728;
    uint32_t Be_base = base + 79872;
    __nv_bfloat16* Ae = (__nv_bfloat16*)(smem + 73728);
    __nv_bfloat16* Be = (__nv_bfloat16*)(smem + 79872);

    for (int idx = tid; idx < 128 * 16; idx += 256) {
        int rr = idx >> 4, j = idx & 15;
        Ae[rr * 24 + j] = __float2bfloat16(g_e[(size_t)(m0 + rr) * NJ + j]);
        if (rr < 64) Be[rr * 24 + j] = __float2bfloat16(bvec[(size_t)j * NU + n0 + rr]);
    }

    const int rlo = lane & 15, chi = lane >> 4;
    int arow[2], asw[2];
    #pragma unroll
    for (int im = 0; im < 2; im++) { arow[im] = wm + im * 16 + rlo; asw[im] = arow[im] & 7; }

    float acc[2][4][4] = {};

    auto load_stage = [&](int ki, int s) {
        const __nv_bfloat16* asrc = g_A2 + (size_t)m0 * JM + ki * 64;
        const __nv_bfloat16* bsrc = g_Wb + (size_t)ki * 64 * NU + n0;
        uint32_t a_s = base + s * 16384;
        uint32_t b_s = Bs_base + s * 8192;
        #pragma unroll
        for (int i = 0; i < 4; i++) {
            int lin = tid + i * 256;
            int r = lin >> 3, c = lin & 7;
            cp16(a_s + r * 128 + ((c ^ (r & 7)) << 4), asrc + (size_t)r * JM + c * 8);
        }
        #pragma unroll
        for (int i = 0; i < 2; i++) {
            int lin = tid + i * 256;
            int r = lin >> 3, c = lin & 7;
            cp16(b_s + r * 128 + ((c ^ (r & 7)) << 4), bsrc + (size_t)r * NU + c * 8);
        }
        cp_commit();
    };

    uint32_t fa[2][2][4], fb[2][2][4];
    auto ldfrag = [&](uint32_t a_s, uint32_t b_s, int kk, int buf) {
        int ch = kk * 2 + chi;
        #pragma unroll
        for (int im = 0; im < 2; im++)
            ldm_x4(fa[buf][im], a_s + arow[im] * 128 + ((ch ^ asw[im]) << 4));
        #pragma unroll
        for (int ib = 0; ib < 2; ib++) {
            int row = kk * 16 + rlo;
            int cb = (wn >> 3) + ib * 2 + chi;
            ldm_x4t(fb[buf][ib], b_s + row * 128 + ((cb ^ (row & 7)) << 4));
        }
    };
    auto domma = [&](int buf) {
        #pragma unroll
        for (int im = 0; im < 2; im++) {
            mma_bf16(acc[im][0], fa[buf][im], fb[buf][0][0], fb[buf][0][1]);
            mma_bf16(acc[im][1], fa[buf][im], fb[buf][0][2], fb[buf][0][3]);
            mma_bf16(acc[im][2], fa[buf][im], fb[buf][1][0], fb[buf][1][1]);
            mma_bf16(acc[im][3], fa[buf][im], fb[buf][1][2], fb[buf][1][3]);
        }
    };
    auto compute = [&](int s) {
        uint32_t a_s = base + s * 16384;
        uint32_t b_s = Bs_base + s * 8192;
        ldfrag(a_s, b_s, 0, 0);
        #pragma unroll
        for (int kk = 0; kk < 4; kk++) {
            if (kk < 3) ldfrag(a_s, b_s, kk + 1, (kk + 1) & 1);
            domma(kk & 1);
        }
    };

    load_stage(0, 0);
    load_stage(1, 1);
    #pragma unroll 1
    for (int ki = 0; ki < 16; ki++) {
        if (ki < 15) cp_wait<1>(); else cp_wait<0>();
        __syncthreads();
        if (ki + 2 < 16) load_stage(ki + 2, (ki + 2) % 3);
        compute(ki % 3);
    }

    {
        uint32_t b[2][4];
        #pragma unroll
        for (int ib = 0; ib < 2; ib++) {
            int row = wn + ib * 16 + rlo;
            ldm_x4(b[ib], Be_base + row * 48 + chi * 16);
        }
        #pragma unroll
        for (int im = 0; im < 2; im++) {
            uint32_t a[4];
            int row = wm + im * 16 + rlo;
            ldm_x4(a, Ae_base + row * 48 + chi * 16);
            mma_bf16(acc[im][0], a, b[0][0], b[0][2]);
            mma_bf16(acc[im][1], a, b[0][1], b[0][3]);
            mma_bf16(acc[im][2], a, b[1][0], b[1][2]);
            mma_bf16(acc[im][3], a, b[1][1], b[1][3]);
        }
    }

    const int qr = lane >> 2;
    const int qc = (lane & 3) * 2;
    #pragma unroll
    for (int im = 0; im < 2; im++) {
        int r0g = m0 + wm + im * 16 + qr;
        float zi0 = 1.0f / g_Z[r0g];
        float zi1 = 1.0f / g_Z[r0g + 8];
        #pragma unroll
        for (int in = 0; in < 4; in++) {
            int cg = n0 + wn + in * 8 + qc;
            float* c = acc[im][in];
            float2 v0 = {c[0] * zi0, c[1] * zi0};
            float2 v1 = {c[2] * zi1, c[3] * zi1};
            *(float2*)&out[(size_t)r0g * NU + cg] = v0;
            *(float2*)&out[(size_t)(r0g + 8) * NU + cg] = v1;
        }
    }
}

// ============================================================
extern "C" void kernel_launch(void* const* d_in, const int* in_sizes, int n_in,
                              void* d_out, int out_size) {
    const float* h    = (const float*)d_in[0];   // [B, F]
    const float* dom  = (const float*)d_in[1];   // [J, M, F]
    const float* W    = (const float*)d_in[2];   // [J, M, U]
    const float* bvec = (const float*)d_in[3];   // [J, U]
    float* out = (float*)d_out;                  // [B, U]

    cudaFuncSetAttribute(front_kernel, cudaFuncAttributeMaxDynamicSharedMemorySize, 32768);
    cudaFuncSetAttribute(gemm1_kernel, cudaFuncAttributeMaxDynamicSharedMemorySize, 49152);
    cudaFuncSetAttribute(gemm2_kernel, cudaFuncAttributeMaxDynamicSharedMemorySize, 82944);

    front_kernel<<<NJ + 640 + 1, 256, 32768>>>(h, dom);
    // zero path (taken when K_hd provably underflows to 0 in fp32):
    bias_kernel<<<BATCH / 4, 256>>>(bvec, out);
    // fallback path (no-ops when g_zero == 1):
    convert_kernel<<<(BATCH + 2 * JM) / 8, 256>>>(h, dom, W);
    gemm1_kernel<<<dim3(JM / 128, BATCH / 128), 256, 49152>>>();
    gemm2_kernel<<<dim3(NU / 64, BATCH / 128), 256, 82944>>>(bvec, out);
}

// round 16
// speedup vs baseline: 2.7297x; 1.2162x over previous
#include <cuda_runtime.h>
#include <cuda_bf16.h>
#include <math.h>
#include <stdint.h>

#define BATCH 4096
#define FDIM  512
#define NJ    16
#define NM    64
#define NU    512
#define JM    (NJ*NM)   // 1024

// ---- scratch (device globals; no allocation allowed) ----
__device__ __nv_bfloat16 g_hb[(size_t)BATCH * FDIM];   // 4 MB
__device__ __nv_bfloat16 g_db[(size_t)JM * FDIM];      // 1 MB
__device__ __nv_bfloat16 g_Wb[(size_t)JM * NU];        // 1 MB
__device__ __nv_bfloat16 g_A2[(size_t)BATCH * JM];     // 8 MB : e-scaled Khd
__device__ float g_h2[BATCH];
__device__ float g_d2[JM];
__device__ float g_kdd[NJ];
__device__ int   g_zero;            // 1 => K_hd provably all-zero in fp32
__device__ int   g_cnt = 0;         // stats completion counter
__device__ int   g_conv = 0;        // fallback convert counter
__device__ int   g_band[BATCH / 128];
__device__ float g_e[BATCH * NJ];
__device__ float g_Z[BATCH];

// ================= PTX helpers =================
__device__ __forceinline__ void cp16(uint32_t dst, const void* src) {
    asm volatile("cp.async.cg.shared.global [%0], [%1], 16;\n" :: "r"(dst), "l"(src));
}
__device__ __forceinline__ void cp_commit() { asm volatile("cp.async.commit_group;\n"); }
template <int N> __device__ __forceinline__ void cp_wait() {
    asm volatile("cp.async.wait_group %0;\n" :: "n"(N));
}
__device__ __forceinline__ void ldm_x4(uint32_t a[4], uint32_t addr) {
    asm volatile("ldmatrix.sync.aligned.m8n8.x4.shared.b16 {%0,%1,%2,%3}, [%4];\n"
                 : "=r"(a[0]), "=r"(a[1]), "=r"(a[2]), "=r"(a[3]) : "r"(addr));
}
__device__ __forceinline__ void ldm_x4t(uint32_t a[4], uint32_t addr) {
    asm volatile("ldmatrix.sync.aligned.m8n8.x4.trans.shared.b16 {%0,%1,%2,%3}, [%4];\n"
                 : "=r"(a[0]), "=r"(a[1]), "=r"(a[2]), "=r"(a[3]) : "r"(addr));
}
__device__ __forceinline__ void mma_bf16(float c[4], const uint32_t a[4], uint32_t b0, uint32_t b1) {
    asm volatile(
        "mma.sync.aligned.m16n8k16.row.col.f32.bf16.bf16.f32 "
        "{%0,%1,%2,%3}, {%4,%5,%6,%7}, {%8,%9}, {%0,%1,%2,%3};\n"
        : "+f"(c[0]), "+f"(c[1]), "+f"(c[2]), "+f"(c[3])
        : "r"(a[0]), "r"(a[1]), "r"(a[2]), "r"(a[3]), "r"(b0), "r"(b1));
}

// ====== front kernel: [0,16)=kdd, [16,656)=stats, 656=decide =============
__global__ void __launch_bounds__(256) front_kernel(const float* __restrict__ h,
                                                    const float* __restrict__ dom) {
    extern __shared__ char smem[];           // 32 KB (kdd blocks only)
    __shared__ float d2s[NM];
    __shared__ float ws[8];
    const int bid = blockIdx.x;
    const int tid = threadIdx.x;
    const int lane = tid & 31, w = tid >> 5;

    if (bid < NJ) {
        // ---------------- kdd block ----------------
        const int j = bid;
        const float* dj = dom + (size_t)j * NM * FDIM;
        uint32_t base = (uint32_t)__cvta_generic_to_shared(smem);
        const int rlo = lane & 15, chi = lane >> 4;
        float acc[8][4] = {};
        float rs[8] = {};
        #pragma unroll 1
        for (int pass = 0; pass < 2; pass++) {
            #pragma unroll
            for (int rr = 0; rr < 8; rr++) {
                int r = w * 8 + rr;
                const float* src = dj + (size_t)r * FDIM + pass * 256;
                int c = lane;
                float4 v0 = *(const float4*)&src[c * 8];
                float4 v1 = *(const float4*)&src[c * 8 + 4];
                rs[rr] += v0.x*v0.x + v0.y*v0.y + v0.z*v0.z + v0.w*v0.w
                        + v1.x*v1.x + v1.y*v1.y + v1.z*v1.z + v1.w*v1.w;
                __nv_bfloat162 p0 = __floats2bfloat162_rn(v0.x, v0.y);
                __nv_bfloat162 p1 = __floats2bfloat162_rn(v0.z, v0.w);
                __nv_bfloat162 p2 = __floats2bfloat162_rn(v1.x, v1.y);
                __nv_bfloat162 p3 = __floats2bfloat162_rn(v1.z, v1.w);
                uint4 u;
                u.x = *(uint32_t*)&p0; u.y = *(uint32_t*)&p1;
                u.z = *(uint32_t*)&p2; u.w = *(uint32_t*)&p3;
                *(uint4*)(smem + r * 512 + ((c ^ (r & 7)) << 4)) = u;
            }
            __syncthreads();
            if (w < 4) {
                #pragma unroll 4
                for (int kk = 0; kk < 16; kk++) {
                    int ch = kk * 2 + chi;
                    uint32_t a[4], b[4][4];
                    {
                        int row = w * 16 + rlo;
                        ldm_x4(a, base + row * 512 + ((ch ^ (row & 7)) << 4));
                    }
                    #pragma unroll
                    for (int nb = 0; nb < 4; nb++) {
                        int row = nb * 16 + rlo;
                        ldm_x4(b[nb], base + row * 512 + ((ch ^ (row & 7)) << 4));
                    }
                    #pragma unroll
                    for (int nb = 0; nb < 4; nb++) {
                        mma_bf16(acc[2*nb],   a, b[nb][0], b[nb][2]);
                        mma_bf16(acc[2*nb+1], a, b[nb][1], b[nb][3]);
                    }
                }
            }
            __syncthreads();
        }
        #pragma unroll
        for (int rr = 0; rr < 8; rr++) {
            float s = rs[rr];
            #pragma unroll
            for (int off = 16; off; off >>= 1) s += __shfl_xor_sync(0xffffffffu, s, off);
            if (lane == 0) d2s[w * 8 + rr] = s;
        }
        __syncthreads();
        if (w < 4) {
            const int qr = lane >> 2;
            const int qc = (lane & 3) * 2;
            int m0 = w * 16 + qr;
            float d2a = d2s[m0], d2b = d2s[m0 + 8];
            float s = 0.f;
            #pragma unroll
            for (int nt = 0; nt < 8; nt++) {
                int n = nt * 8 + qc;
                float d2x = d2s[n], d2y = d2s[n + 1];
                float* c = acc[nt];
                s += expf(-2.f * (d2a + d2x - 2.f * c[0]));
                s += expf(-2.f * (d2a + d2y - 2.f * c[1]));
                s += expf(-2.f * (d2b + d2x - 2.f * c[2]));
                s += expf(-2.f * (d2b + d2y - 2.f * c[3]));
            }
            #pragma unroll
            for (int off = 16; off; off >>= 1) s += __shfl_xor_sync(0xffffffffu, s, off);
            if (lane == 0) ws[w] = s;
        }
        __syncthreads();
        if (tid == 0) g_kdd[j] = (ws[0] + ws[1] + ws[2] + ws[3]) * (1.0f / (NM * NM));
        return;
    }

    if (bid < NJ + 640) {
        // ---------------- stats block: 8 rows of h/dom ----------------
        int warp = (bid - NJ) * 8 + w;
        const float* p;
        float* o;
        if (warp < BATCH) {
            p = h + (size_t)warp * FDIM; o = &g_h2[warp];
            if (lane == 0) g_Z[warp] = 0.f;
        } else {
            int r = warp - BATCH;
            p = dom + (size_t)r * FDIM; o = &g_d2[r];
        }
        float s = 0.f;
        #pragma unroll
        for (int i = 0; i < 4; i++) {
            float4 v = *(const float4*)&p[(lane + i * 32) << 2];
            s += v.x*v.x + v.y*v.y + v.z*v.z + v.w*v.w;
        }
        #pragma unroll
        for (int off = 16; off; off >>= 1) s += __shfl_xor_sync(0xffffffffu, s, off);
        if (lane == 0) *o = s;
        __syncthreads();
        if (tid == 0) {
            __threadfence();
            atomicAdd(&g_cnt, 1);
        }
        return;
    }

    // ---------------- decide block ----------------
    {
        __shared__ float mn[8], mx[8];
        if (tid == 0) {
            while (atomicAdd(&g_cnt, 0) < 640) { }
            atomicExch(&g_cnt, 0);     // reset for next graph replay
            atomicExch(&g_conv, 0);    // reset fallback counters
        }
        if (tid < BATCH / 128) g_band[tid] = 0;
        __syncthreads();
        __threadfence();
        float h2min = 3.4e38f;
        for (int i = tid; i < BATCH; i += 256) h2min = fminf(h2min, g_h2[i]);
        float d2max = 0.f;
        for (int i = tid; i < JM; i += 256) d2max = fmaxf(d2max, g_d2[i]);
        #pragma unroll
        for (int off = 16; off; off >>= 1) {
            h2min = fminf(h2min, __shfl_xor_sync(0xffffffffu, h2min, off));
            d2max = fmaxf(d2max, __shfl_xor_sync(0xffffffffu, d2max, off));
        }
        if (lane == 0) { mn[w] = h2min; mx[w] = d2max; }
        __syncthreads();
        if (tid == 0) {
            float a = 3.4e38f, b = 0.f;
            #pragma unroll
            for (int i = 0; i < 8; i++) { a = fminf(a, mn[i]); b = fmaxf(b, mx[i]); }
            float diff = sqrtf(a) - sqrtf(b);
            // Cauchy-Schwarz: sqdist >= (sqrt(h2)-sqrt(d2))^2 >= 60
            // => exponent <= -120 => fp32 exp underflows to 0 everywhere.
            g_zero = (diff > 0.f && diff * diff >= 60.f) ? 1 : 0;
        }
    }
}

// ====== uber kernel: zero path = bias broadcast; else full fallback ======
// grid = 1280.  zero: blocks [0,1024) write out (4 rows each).
// fallback: [0,768)=convert, [768,1024)=gemm1 tiles, [1024,1280)=gemm2.
__global__ void __launch_bounds__(256, 2) uber_kernel(const float* __restrict__ h,
                                                      const float* __restrict__ dom,
                                                      const float* __restrict__ W,
                                                      const float* __restrict__ bvec,
                                                      float* __restrict__ out) {
    extern __shared__ char smem[];          // 48 KB dynamic
    const int bid = blockIdx.x;
    const int tid = threadIdx.x;
    const int lane = tid & 31, wid = tid >> 5;

    if (g_zero) {
        // ------------- bias path: out[b,:] = sum_j prob_j * bvec[j,:] ----
        if (bid >= BATCH / 4) return;
        __shared__ float es0[NJ];
        if (tid < NJ) es0[tid] = expf(-1.0f - g_kdd[tid]);
        __syncthreads();
        float Z = 0.f;
        #pragma unroll
        for (int j = 0; j < NJ; j++) Z += es0[j];
        float inv = 1.0f / Z;
        int u0 = tid * 2;
        float cx = 0.f, cy = 0.f;
        #pragma unroll
        for (int j = 0; j < NJ; j++) {
            float p = es0[j] * inv;
            float2 bv = *(const float2*)&bvec[(size_t)j * NU + u0];
            cx += p * bv.x;
            cy += p * bv.y;
        }
        float2 o = {cx, cy};
        int r0 = bid * 4;
        #pragma unroll
        for (int r = 0; r < 4; r++)
            *(float2*)&out[(size_t)(r0 + r) * NU + u0] = o;
        return;
    }

    // =================== fallback path (g_zero == 0) =====================
    uint32_t base = (uint32_t)__cvta_generic_to_shared(smem);
    const int rlo = lane & 15, chi = lane >> 4;

    if (bid < 768) {
        // ---------------- convert block: 8 rows fp32 -> bf16 -------------
        int warp = bid * 8 + wid;
        const float* p;
        __nv_bfloat16* dst;
        if (warp < BATCH) {
            p = h + (size_t)warp * FDIM; dst = g_hb + (size_t)warp * FDIM;
        } else if (warp < BATCH + JM) {
            int r = warp - BATCH;
            p = dom + (size_t)r * FDIM; dst = g_db + (size_t)r * FDIM;
        } else {
            int r = warp - BATCH - JM;
            p = W + (size_t)r * NU; dst = g_Wb + (size_t)r * NU;
        }
        #pragma unroll
        for (int i = 0; i < 4; i++) {
            int idx = (lane + i * 32) << 2;
            float4 v = *(const float4*)&p[idx];
            __nv_bfloat162 o0 = __floats2bfloat162_rn(v.x, v.y);
            __nv_bfloat162 o1 = __floats2bfloat162_rn(v.z, v.w);
            uint2 u; u.x = *(uint32_t*)&o0; u.y = *(uint32_t*)&o1;
            *(uint2*)&dst[idx] = u;
        }
        __syncthreads();
        if (tid == 0) {
            __threadfence();
            atomicAdd(&g_conv, 1);
        }
        return;
    }

    if (bid < 1024) {
        // ---------------- gemm1 tile block --------------------------------
        __shared__ float jp[128][2];
        __shared__ float es[128][2];
        __shared__ float kddm[2];
        const int t = bid - 768;
        const int bx = t & 7, by = t >> 3;
        const int wm = (wid >> 2) * 64;
        const int wn = (wid & 3) * 32;
        const int m0 = by * 128;
        const int n0 = bx * 128;
        const int j0 = bx * 2;

        if (tid == 0) {
            while (atomicAdd(&g_conv, 0) < 768) { }
        }
        if (tid < 256) { jp[tid >> 1][tid & 1] = 0.f; }
        if (tid < 2) kddm[tid] = g_kdd[j0 + tid];
        __syncthreads();
        __threadfence();

        int arow[4], asw[4], brow[2], bsw[2];
        #pragma unroll
        for (int im = 0; im < 4; im++) { arow[im] = wm + im * 16 + rlo; asw[im] = (arow[im] >> 1) & 3; }
        #pragma unroll
        for (int ib = 0; ib < 2; ib++) { brow[ib] = wn + ib * 16 + rlo; bsw[ib] = (brow[ib] >> 1) & 3; }

        float acc[4][4][4] = {};

        auto load_stage = [&](int ki, int s) {
            const __nv_bfloat16* ha = g_hb + (size_t)m0 * FDIM + ki * 32;
            const __nv_bfloat16* da = g_db + (size_t)n0 * FDIM + ki * 32;
            uint32_t a_s = base + s * 16384;
            uint32_t b_s = a_s + 8192;
            #pragma unroll
            for (int i = 0; i < 2; i++) {
                int lin = tid + i * 256;
                int r = lin >> 2, c = lin & 3;
                uint32_t off = (uint32_t)(r * 64 + (((c ^ ((r >> 1) & 3))) << 4));
                cp16(a_s + off, ha + (size_t)r * FDIM + c * 8);
                cp16(b_s + off, da + (size_t)r * FDIM + c * 8);
            }
            cp_commit();
        };

        auto compute = [&](int s) {
            uint32_t a_s = base + s * 16384;
            uint32_t b_s = a_s + 8192;
            #pragma unroll
            for (int kk = 0; kk < 2; kk++) {
                int ch = kk * 2 + chi;
                uint32_t a[4][4], b[2][4];
                #pragma unroll
                for (int im = 0; im < 4; im++)
                    ldm_x4(a[im], a_s + arow[im] * 64 + ((ch ^ asw[im]) << 4));
                #pragma unroll
                for (int ib = 0; ib < 2; ib++)
                    ldm_x4(b[ib], b_s + brow[ib] * 64 + ((ch ^ bsw[ib]) << 4));
                #pragma unroll
                for (int im = 0; im < 4; im++) {
                    mma_bf16(acc[im][0], a[im], b[0][0], b[0][2]);
                    mma_bf16(acc[im][1], a[im], b[0][1], b[0][3]);
                    mma_bf16(acc[im][2], a[im], b[1][0], b[1][2]);
                    mma_bf16(acc[im][3], a[im], b[1][1], b[1][3]);
                }
            }
        };

        load_stage(0, 0);
        load_stage(1, 1);
        #pragma unroll 1
        for (int ki = 0; ki < 16; ki++) {
            if (ki < 15) cp_wait<1>(); else cp_wait<0>();
            __syncthreads();
            if (ki + 2 < 16) load_stage(ki + 2, (ki + 2) % 3);
            compute(ki % 3);
        }

        const int qr = lane >> 2;
        const int qc = (lane & 3) * 2;
        const int jj = wn >> 6;
        #pragma unroll
        for (int im = 0; im < 4; im++) {
            int r0g = m0 + wm + im * 16 + qr;
            float h2a = g_h2[r0g], h2b = g_h2[r0g + 8];
            float rs0 = 0.f, rs1 = 0.f;
            #pragma unroll
            for (int in = 0; in < 4; in++) {
                int cg = n0 + wn + in * 8 + qc;
                float d2x = g_d2[cg], d2y = g_d2[cg + 1];
                float* c = acc[im][in];
                c[0] = expf(4.f * c[0] - 2.f * (h2a + d2x));
                c[1] = expf(4.f * c[1] - 2.f * (h2a + d2y));
                c[2] = expf(4.f * c[2] - 2.f * (h2b + d2x));
                c[3] = expf(4.f * c[3] - 2.f * (h2b + d2y));
                rs0 += c[0] + c[1];
                rs1 += c[2] + c[3];
            }
            rs0 += __shfl_xor_sync(0xffffffffu, rs0, 1);
            rs0 += __shfl_xor_sync(0xffffffffu, rs0, 2);
            rs1 += __shfl_xor_sync(0xffffffffu, rs1, 1);
            rs1 += __shfl_xor_sync(0xffffffffu, rs1, 2);
            if ((lane & 3) == 0) {
                atomicAdd(&jp[wm + im * 16 + qr][jj], rs0);
                atomicAdd(&jp[wm + im * 16 + qr + 8][jj], rs1);
            }
        }
        __syncthreads();
        if (tid < 256) {
            int rl = tid >> 1, j = tid & 1;
            float jsum = jp[rl][j];
            float e = expf(jsum * (1.0f / 32.0f) - 1.0f - kddm[j]);
            es[rl][j] = e;
            g_e[(m0 + rl) * NJ + j0 + j] = e;
            atomicAdd(&g_Z[m0 + rl], e);
        }
        __syncthreads();
        #pragma unroll
        for (int im = 0; im < 4; im++) {
            int rl = wm + im * 16 + qr;
            int r0g = m0 + rl;
            float e0 = es[rl][jj], e1 = es[rl + 8][jj];
            #pragma unroll
            for (int in = 0; in < 4; in++) {
                int cg = n0 + wn + in * 8 + qc;
                float* c = acc[im][in];
                *(__nv_bfloat162*)&g_A2[(size_t)r0g * JM + cg] =
                    __floats2bfloat162_rn(c[0] * e0, c[1] * e0);
                *(__nv_bfloat162*)&g_A2[(size_t)(r0g + 8) * JM + cg] =
                    __floats2bfloat162_rn(c[2] * e1, c[3] * e1);
            }
        }
        __syncthreads();
        if (tid == 0) {
            __threadfence();
            atomicAdd(&g_band[by], 1);
        }
        return;
    }

    // ---------------- gemm2 tile block (BK=32, 3-stage) -------------------
    {
        __shared__ __align__(16) __nv_bfloat16 Ae[128][24];
        __shared__ __align__(16) __nv_bfloat16 Be[64][24];
        const int t = bid - 1024;
        const int nx = t & 7, my = t >> 3;
        const int wm = (wid >> 1) * 32;
        const int wn = (wid & 1) * 32;
        const int m0 = my * 128;
        const int n0 = nx * 64;

        if (tid == 0) {
            while (atomicAdd(&g_band[my], 0) < 8) { }
        }
        __syncthreads();
        __threadfence();

        for (int idx = tid; idx < 128 * 16; idx += 256) {
            int rr = idx >> 4, j = idx & 15;
            Ae[rr][j] = __float2bfloat16(*((volatile float*)&g_e[(size_t)(m0 + rr) * NJ + j]));
            if (rr < 64) Be[rr][j] = __float2bfloat16(bvec[(size_t)j * NU + n0 + rr]);
        }

        uint32_t Bs_base = base + 24576;
        uint32_t Ae_base = (uint32_t)__cvta_generic_to_shared(Ae);
        uint32_t Be_base = (uint32_t)__cvta_generic_to_shared(Be);

        int arow[2], asw[2];
        #pragma unroll
        for (int im = 0; im < 2; im++) { arow[im] = wm + im * 16 + rlo; asw[im] = (arow[im] >> 1) & 3; }

        float acc[2][4][4] = {};

        auto load_stage = [&](int ki, int s) {
            const __nv_bfloat16* asrc = g_A2 + (size_t)m0 * JM + ki * 32;
            const __nv_bfloat16* bsrc = g_Wb + (size_t)ki * 32 * NU + n0;
            uint32_t a_s = base + s * 8192;
            uint32_t b_s = Bs_base + s * 4096;
            #pragma unroll
            for (int i = 0; i < 2; i++) {
                int lin = tid + i * 256;
                int r = lin >> 2, c = lin & 3;
                cp16(a_s + r * 64 + ((c ^ ((r >> 1) & 3)) << 4),
                     asrc + (size_t)r * JM + c * 8);
            }
            {
                int r = tid >> 3, c = tid & 7;
                cp16(b_s + r * 128 + ((c ^ (r & 7)) << 4),
                     bsrc + (size_t)r * NU + c * 8);
            }
            cp_commit();
        };

        auto compute = [&](int s) {
            uint32_t a_s = base + s * 8192;
            uint32_t b_s = Bs_base + s * 4096;
            #pragma unroll
            for (int kk = 0; kk < 2; kk++) {
                int ch = kk * 2 + chi;
                uint32_t a[2][4], b[2][4];
                #pragma unroll
                for (int im = 0; im < 2; im++)
                    ldm_x4(a[im], a_s + arow[im] * 64 + ((ch ^ asw[im]) << 4));
                #pragma unroll
                for (int ib = 0; ib < 2; ib++) {
                    int row = kk * 16 + rlo;
                    int cb = (wn >> 3) + ib * 2 + chi;
                    ldm_x4t(b[ib], b_s + row * 128 + ((cb ^ (row & 7)) << 4));
                }
                #pragma unroll
                for (int im = 0; im < 2; im++) {
                    mma_bf16(acc[im][0], a[im], b[0][0], b[0][1]);
                    mma_bf16(acc[im][1], a[im], b[0][2], b[0][3]);
                    mma_bf16(acc[im][2], a[im], b[1][0], b[1][1]);
                    mma_bf16(acc[im][3], a[im], b[1][2], b[1][3]);
                }
            }
        };

        load_stage(0, 0);
        load_stage(1, 1);
        #pragma unroll 1
        for (int ki = 0; ki < 32; ki++) {
            if (ki < 31) cp_wait<1>(); else cp_wait<0>();
            __syncthreads();
            if (ki + 2 < 32) load_stage(ki + 2, (ki + 2) % 3);
            compute(ki % 3);
        }

        // bias fold
        {
            uint32_t b[2][4];
            #pragma unroll
            for (int ib = 0; ib < 2; ib++) {
                int row = wn + ib * 16 + rlo;
                ldm_x4(b[ib], Be_base + row * 48 + chi * 16);
            }
            #pragma unroll
            for (int im = 0; im < 2; im++) {
                uint32_t a[4];
                int row = wm + im * 16 + rlo;
                ldm_x4(a, Ae_base + row * 48 + chi * 16);
                mma_bf16(acc[im][0], a, b[0][0], b[0][2]);
                mma_bf16(acc[im][1], a, b[0][1], b[0][3]);
                mma_bf16(acc[im][2], a, b[1][0], b[1][2]);
                mma_bf16(acc[im][3], a, b[1][1], b[1][3]);
            }
        }

        const int qr = lane >> 2;
        const int qc = (lane & 3) * 2;
        #pragma unroll
        for (int im = 0; im < 2; im++) {
            int r0g = m0 + wm + im * 16 + qr;
            float zi0 = 1.0f / *((volatile float*)&g_Z[r0g]);
            float zi1 = 1.0f / *((volatile float*)&g_Z[r0g + 8]);
            #pragma unroll
            for (int in = 0; in < 4; in++) {
                int cg = n0 + wn + in * 8 + qc;
                float* c = acc[im][in];
                float2 v0 = {c[0] * zi0, c[1] * zi0};
                float2 v1 = {c[2] * zi1, c[3] * zi1};
                *(float2*)&out[(size_t)r0g * NU + cg] = v0;
                *(float2*)&out[(size_t)(r0g + 8) * NU + cg] = v1;
            }
        }
    }
}

// ============================================================
extern "C" void kernel_launch(void* const* d_in, const int* in_sizes, int n_in,
                              void* d_out, int out_size) {
    const float* h    = (const float*)d_in[0];   // [B, F]
    const float* dom  = (const float*)d_in[1];   // [J, M, F]
    const float* W    = (const float*)d_in[2];   // [J, M, U]
    const float* bvec = (const float*)d_in[3];   // [J, U]
    float* out = (float*)d_out;                  // [B, U]

    cudaFuncSetAttribute(front_kernel, cudaFuncAttributeMaxDynamicSharedMemorySize, 32768);
    cudaFuncSetAttribute(uber_kernel,  cudaFuncAttributeMaxDynamicSharedMemorySize, 49152);

    front_kernel<<<NJ + 640 + 1, 256, 32768>>>(h, dom);
    uber_kernel<<<1280, 256, 49152>>>(h, dom, W, bvec, out);
}

// round 17
// speedup vs baseline: 2.7958x; 1.0242x over previous
#include <cuda_runtime.h>
#include <cuda_bf16.h>
#include <math.h>
#include <stdint.h>

#define BATCH 4096
#define FDIM  512
#define NJ    16
#define NM    64
#define NU    512
#define JM    (NJ*NM)   // 1024

// ---- scratch (device globals; no allocation allowed) ----
__device__ __nv_bfloat16 g_hb[(size_t)BATCH * FDIM];   // 4 MB
__device__ __nv_bfloat16 g_db[(size_t)JM * FDIM];      // 1 MB
__device__ __nv_bfloat16 g_Wb[(size_t)JM * NU];        // 1 MB
__device__ __nv_bfloat16 g_A2[(size_t)BATCH * JM];     // 8 MB : e-scaled Khd
__device__ float g_h2[BATCH];
__device__ float g_d2[JM];
__device__ float g_kdd[NJ];
__device__ int   g_zero;            // 1 => K_hd provably all-zero in fp32
__device__ int   g_cnt = 0;         // stats completion counter
__device__ int   g_conv = 0;        // fallback convert counter
__device__ int   g_band[BATCH / 128];
__device__ float g_e[BATCH * NJ];
__device__ float g_Z[BATCH];

// ================= PTX helpers =================
__device__ __forceinline__ void cp16(uint32_t dst, const void* src) {
    asm volatile("cp.async.cg.shared.global [%0], [%1], 16;\n" :: "r"(dst), "l"(src));
}
__device__ __forceinline__ void cp_commit() { asm volatile("cp.async.commit_group;\n"); }
template <int N> __device__ __forceinline__ void cp_wait() {
    asm volatile("cp.async.wait_group %0;\n" :: "n"(N));
}
__device__ __forceinline__ void ldm_x4(uint32_t a[4], uint32_t addr) {
    asm volatile("ldmatrix.sync.aligned.m8n8.x4.shared.b16 {%0,%1,%2,%3}, [%4];\n"
                 : "=r"(a[0]), "=r"(a[1]), "=r"(a[2]), "=r"(a[3]) : "r"(addr));
}
__device__ __forceinline__ void ldm_x4t(uint32_t a[4], uint32_t addr) {
    asm volatile("ldmatrix.sync.aligned.m8n8.x4.trans.shared.b16 {%0,%1,%2,%3}, [%4];\n"
                 : "=r"(a[0]), "=r"(a[1]), "=r"(a[2]), "=r"(a[3]) : "r"(addr));
}
__device__ __forceinline__ void mma_bf16(float c[4], const uint32_t a[4], uint32_t b0, uint32_t b1) {
    asm volatile(
        "mma.sync.aligned.m16n8k16.row.col.f32.bf16.bf16.f32 "
        "{%0,%1,%2,%3}, {%4,%5,%6,%7}, {%8,%9}, {%0,%1,%2,%3};\n"
        : "+f"(c[0]), "+f"(c[1]), "+f"(c[2]), "+f"(c[3])
        : "r"(a[0]), "r"(a[1]), "r"(a[2]), "r"(a[3]), "r"(b0), "r"(b1));
}

// ====== front kernel: [0,16)=kdd, [16,656)=stats, 656=decide =============
__global__ void __launch_bounds__(256) front_kernel(const float* __restrict__ h,
                                                    const float* __restrict__ dom) {
    extern __shared__ char smem[];           // 32 KB (kdd blocks only)
    __shared__ float d2s[NM];
    __shared__ float ws[8];
    const int bid = blockIdx.x;
    const int tid = threadIdx.x;
    const int lane = tid & 31, w = tid >> 5;

    if (bid < NJ) {
        // ---------------- kdd block (8-warp MMA split) ----------------
        const int j = bid;
        const float* dj = dom + (size_t)j * NM * FDIM;
        uint32_t base = (uint32_t)__cvta_generic_to_shared(smem);
        const int rlo = lane & 15, chi = lane >> 4;
        const int wm = (w >> 1) * 16;       // m quadrant
        const int nh = (w & 1) * 2;         // n-half: nb in {nh, nh+1}
        float acc[4][4] = {};
        float rs[8] = {};
        #pragma unroll 1
        for (int pass = 0; pass < 2; pass++) {
            #pragma unroll
            for (int rr = 0; rr < 8; rr++) {
                int r = w * 8 + rr;
                const float* src = dj + (size_t)r * FDIM + pass * 256;
                int c = lane;
                float4 v0 = *(const float4*)&src[c * 8];
                float4 v1 = *(const float4*)&src[c * 8 + 4];
                rs[rr] += v0.x*v0.x + v0.y*v0.y + v0.z*v0.z + v0.w*v0.w
                        + v1.x*v1.x + v1.y*v1.y + v1.z*v1.z + v1.w*v1.w;
                __nv_bfloat162 p0 = __floats2bfloat162_rn(v0.x, v0.y);
                __nv_bfloat162 p1 = __floats2bfloat162_rn(v0.z, v0.w);
                __nv_bfloat162 p2 = __floats2bfloat162_rn(v1.x, v1.y);
                __nv_bfloat162 p3 = __floats2bfloat162_rn(v1.z, v1.w);
                uint4 u;
                u.x = *(uint32_t*)&p0; u.y = *(uint32_t*)&p1;
                u.z = *(uint32_t*)&p2; u.w = *(uint32_t*)&p3;
                *(uint4*)(smem + r * 512 + ((c ^ (r & 7)) << 4)) = u;
            }
            __syncthreads();
            #pragma unroll 4
            for (int kk = 0; kk < 16; kk++) {
                int ch = kk * 2 + chi;
                uint32_t a[4], b[2][4];
                {
                    int row = wm + rlo;
                    ldm_x4(a, base + row * 512 + ((ch ^ (row & 7)) << 4));
                }
                #pragma unroll
                for (int nbi = 0; nbi < 2; nbi++) {
                    int row = (nh + nbi) * 16 + rlo;
                    ldm_x4(b[nbi], base + row * 512 + ((ch ^ (row & 7)) << 4));
                }
                #pragma unroll
                for (int nbi = 0; nbi < 2; nbi++) {
                    mma_bf16(acc[2*nbi],   a, b[nbi][0], b[nbi][2]);
                    mma_bf16(acc[2*nbi+1], a, b[nbi][1], b[nbi][3]);
                }
            }
            __syncthreads();
        }
        #pragma unroll
        for (int rr = 0; rr < 8; rr++) {
            float s = rs[rr];
            #pragma unroll
            for (int off = 16; off; off >>= 1) s += __shfl_xor_sync(0xffffffffu, s, off);
            if (lane == 0) d2s[w * 8 + rr] = s;
        }
        __syncthreads();
        {
            const int qr = lane >> 2;
            const int qc = (lane & 3) * 2;
            int m0 = wm + qr;
            float d2a = d2s[m0], d2b = d2s[m0 + 8];
            float s = 0.f;
            #pragma unroll
            for (int nt = 0; nt < 4; nt++) {
                int ntg = (w & 1) * 4 + nt;
                int n = ntg * 8 + qc;
                float d2x = d2s[n], d2y = d2s[n + 1];
                float* c = acc[nt];
                s += expf(-2.f * (d2a + d2x - 2.f * c[0]));
                s += expf(-2.f * (d2a + d2y - 2.f * c[1]));
                s += expf(-2.f * (d2b + d2x - 2.f * c[2]));
                s += expf(-2.f * (d2b + d2y - 2.f * c[3]));
            }
            #pragma unroll
            for (int off = 16; off; off >>= 1) s += __shfl_xor_sync(0xffffffffu, s, off);
            if (lane == 0) ws[w] = s;
        }
        __syncthreads();
        if (tid == 0) {
            float t = 0.f;
            #pragma unroll
            for (int i = 0; i < 8; i++) t += ws[i];
            g_kdd[j] = t * (1.0f / (NM * NM));
        }
        return;
    }

    if (bid < NJ + 640) {
        // ---------------- stats block: 8 rows of h/dom ----------------
        int warp = (bid - NJ) * 8 + w;
        const float* p;
        float* o;
        if (warp < BATCH) {
            p = h + (size_t)warp * FDIM; o = &g_h2[warp];
            if (lane == 0) g_Z[warp] = 0.f;
        } else {
            int r = warp - BATCH;
            p = dom + (size_t)r * FDIM; o = &g_d2[r];
        }
        float s = 0.f;
        #pragma unroll
        for (int i = 0; i < 4; i++) {
            float4 v = *(const float4*)&p[(lane + i * 32) << 2];
            s += v.x*v.x + v.y*v.y + v.z*v.z + v.w*v.w;
        }
        #pragma unroll
        for (int off = 16; off; off >>= 1) s += __shfl_xor_sync(0xffffffffu, s, off);
        if (lane == 0) *o = s;
        __syncthreads();
        if (tid == 0) {
            __threadfence();
            atomicAdd(&g_cnt, 1);
        }
        return;
    }

    // ---------------- decide block ----------------
    {
        __shared__ float mn[8], mx[8];
        if (tid == 0) {
            while (atomicAdd(&g_cnt, 0) < 640) { }
            atomicExch(&g_cnt, 0);     // reset for next graph replay
            atomicExch(&g_conv, 0);    // reset fallback counters
        }
        if (tid < BATCH / 128) g_band[tid] = 0;
        __syncthreads();
        __threadfence();
        float h2min = 3.4e38f;
        for (int i = tid; i < BATCH; i += 256) h2min = fminf(h2min, g_h2[i]);
        float d2max = 0.f;
        for (int i = tid; i < JM; i += 256) d2max = fmaxf(d2max, g_d2[i]);
        #pragma unroll
        for (int off = 16; off; off >>= 1) {
            h2min = fminf(h2min, __shfl_xor_sync(0xffffffffu, h2min, off));
            d2max = fmaxf(d2max, __shfl_xor_sync(0xffffffffu, d2max, off));
        }
        if (lane == 0) { mn[w] = h2min; mx[w] = d2max; }
        __syncthreads();
        if (tid == 0) {
            float a = 3.4e38f, b = 0.f;
            #pragma unroll
            for (int i = 0; i < 8; i++) { a = fminf(a, mn[i]); b = fmaxf(b, mx[i]); }
            float diff = sqrtf(a) - sqrtf(b);
            // Cauchy-Schwarz: sqdist >= (sqrt(h2)-sqrt(d2))^2 >= 60
            // => exponent <= -120 => fp32 exp underflows to 0 everywhere.
            g_zero = (diff > 0.f && diff * diff >= 60.f) ? 1 : 0;
        }
    }
}

// ====== uber kernel: zero path = bias broadcast; else full fallback ======
// zero: 256 blocks x 16 rows, float4 stores (single wave).
// fallback: [0,768)=convert, [768,1024)=gemm1 tiles, [1024,1280)=gemm2.
__global__ void __launch_bounds__(256, 2) uber_kernel(const float* __restrict__ h,
                                                      const float* __restrict__ dom,
                                                      const float* __restrict__ W,
                                                      const float* __restrict__ bvec,
                                                      float* __restrict__ out) {
    extern __shared__ char smem[];          // 48 KB dynamic
    const int bid = blockIdx.x;
    const int tid = threadIdx.x;
    const int lane = tid & 31, wid = tid >> 5;

    if (g_zero) {
        // ------------- bias path: out[b,:] = sum_j prob_j * bvec[j,:] ----
        if (bid >= 256) return;
        __shared__ float es0[NJ];
        if (tid < NJ) es0[tid] = expf(-1.0f - g_kdd[tid]);
        __syncthreads();
        float Z = 0.f;
        #pragma unroll
        for (int j = 0; j < NJ; j++) Z += es0[j];
        float inv = 1.0f / Z;
        int cg = (tid & 127) * 4;        // column group (float4)
        int rhalf = tid >> 7;            // 0 or 1
        float4 acc = {0.f, 0.f, 0.f, 0.f};
        #pragma unroll
        for (int j = 0; j < NJ; j++) {
            float p = es0[j] * inv;
            float4 bv = *(const float4*)&bvec[(size_t)j * NU + cg];
            acc.x += p * bv.x; acc.y += p * bv.y;
            acc.z += p * bv.z; acc.w += p * bv.w;
        }
        int r0 = bid * 16 + rhalf * 8;
        #pragma unroll
        for (int r = 0; r < 8; r++)
            *(float4*)&out[(size_t)(r0 + r) * NU + cg] = acc;
        return;
    }

    // =================== fallback path (g_zero == 0) =====================
    uint32_t base = (uint32_t)__cvta_generic_to_shared(smem);
    const int rlo = lane & 15, chi = lane >> 4;

    if (bid < 768) {
        // ---------------- convert block: 8 rows fp32 -> bf16 -------------
        int warp = bid * 8 + wid;
        const float* p;
        __nv_bfloat16* dst;
        if (warp < BATCH) {
            p = h + (size_t)warp * FDIM; dst = g_hb + (size_t)warp * FDIM;
        } else if (warp < BATCH + JM) {
            int r = warp - BATCH;
            p = dom + (size_t)r * FDIM; dst = g_db + (size_t)r * FDIM;
        } else {
            int r = warp - BATCH - JM;
            p = W + (size_t)r * NU; dst = g_Wb + (size_t)r * NU;
        }
        #pragma unroll
        for (int i = 0; i < 4; i++) {
            int idx = (lane + i * 32) << 2;
            float4 v = *(const float4*)&p[idx];
            __nv_bfloat162 o0 = __floats2bfloat162_rn(v.x, v.y);
            __nv_bfloat162 o1 = __floats2bfloat162_rn(v.z, v.w);
            uint2 u; u.x = *(uint32_t*)&o0; u.y = *(uint32_t*)&o1;
            *(uint2*)&dst[idx] = u;
        }
        __syncthreads();
        if (tid == 0) {
            __threadfence();
            atomicAdd(&g_conv, 1);
        }
        return;
    }

    if (bid < 1024) {
        // ---------------- gemm1 tile block --------------------------------
        __shared__ float jp[128][2];
        __shared__ float es[128][2];
        __shared__ float kddm[2];
        const int t = bid - 768;
        const int bx = t & 7, by = t >> 3;
        const int wm = (wid >> 2) * 64;
        const int wn = (wid & 3) * 32;
        const int m0 = by * 128;
        const int n0 = bx * 128;
        const int j0 = bx * 2;

        if (tid == 0) {
            while (atomicAdd(&g_conv, 0) < 768) { }
        }
        if (tid < 256) { jp[tid >> 1][tid & 1] = 0.f; }
        if (tid < 2) kddm[tid] = g_kdd[j0 + tid];
        __syncthreads();
        __threadfence();

        int arow[4], asw[4], brow[2], bsw[2];
        #pragma unroll
        for (int im = 0; im < 4; im++) { arow[im] = wm + im * 16 + rlo; asw[im] = (arow[im] >> 1) & 3; }
        #pragma unroll
        for (int ib = 0; ib < 2; ib++) { brow[ib] = wn + ib * 16 + rlo; bsw[ib] = (brow[ib] >> 1) & 3; }

        float acc[4][4][4] = {};

        auto load_stage = [&](int ki, int s) {
            const __nv_bfloat16* ha = g_hb + (size_t)m0 * FDIM + ki * 32;
            const __nv_bfloat16* da = g_db + (size_t)n0 * FDIM + ki * 32;
            uint32_t a_s = base + s * 16384;
            uint32_t b_s = a_s + 8192;
            #pragma unroll
            for (int i = 0; i < 2; i++) {
                int lin = tid + i * 256;
                int r = lin >> 2, c = lin & 3;
                uint32_t off = (uint32_t)(r * 64 + (((c ^ ((r >> 1) & 3))) << 4));
                cp16(a_s + off, ha + (size_t)r * FDIM + c * 8);
                cp16(b_s + off, da + (size_t)r * FDIM + c * 8);
            }
            cp_commit();
        };

        auto compute = [&](int s) {
            uint32_t a_s = base + s * 16384;
            uint32_t b_s = a_s + 8192;
            #pragma unroll
            for (int kk = 0; kk < 2; kk++) {
                int ch = kk * 2 + chi;
                uint32_t a[4][4], b[2][4];
                #pragma unroll
                for (int im = 0; im < 4; im++)
                    ldm_x4(a[im], a_s + arow[im] * 64 + ((ch ^ asw[im]) << 4));
                #pragma unroll
                for (int ib = 0; ib < 2; ib++)
                    ldm_x4(b[ib], b_s + brow[ib] * 64 + ((ch ^ bsw[ib]) << 4));
                #pragma unroll
                for (int im = 0; im < 4; im++) {
                    mma_bf16(acc[im][0], a[im], b[0][0], b[0][2]);
                    mma_bf16(acc[im][1], a[im], b[0][1], b[0][3]);
                    mma_bf16(acc[im][2], a[im], b[1][0], b[1][2]);
                    mma_bf16(acc[im][3], a[im], b[1][1], b[1][3]);
                }
            }
        };

        load_stage(0, 0);
        load_stage(1, 1);
        #pragma unroll 1
        for (int ki = 0; ki < 16; ki++) {
            if (ki < 15) cp_wait<1>(); else cp_wait<0>();
            __syncthreads();
            if (ki + 2 < 16) load_stage(ki + 2, (ki + 2) % 3);
            compute(ki % 3);
        }

        const int qr = lane >> 2;
        const int qc = (lane & 3) * 2;
        const int jj = wn >> 6;
        #pragma unroll
        for (int im = 0; im < 4; im++) {
            int r0g = m0 + wm + im * 16 + qr;
            float h2a = g_h2[r0g], h2b = g_h2[r0g + 8];
            float rs0 = 0.f, rs1 = 0.f;
            #pragma unroll
            for (int in = 0; in < 4; in++) {
                int cg = n0 + wn + in * 8 + qc;
                float d2x = g_d2[cg], d2y = g_d2[cg + 1];
                float* c = acc[im][in];
                c[0] = expf(4.f * c[0] - 2.f * (h2a + d2x));
                c[1] = expf(4.f * c[1] - 2.f * (h2a + d2y));
                c[2] = expf(4.f * c[2] - 2.f * (h2b + d2x));
                c[3] = expf(4.f * c[3] - 2.f * (h2b + d2y));
                rs0 += c[0] + c[1];
                rs1 += c[2] + c[3];
            }
            rs0 += __shfl_xor_sync(0xffffffffu, rs0, 1);
            rs0 += __shfl_xor_sync(0xffffffffu, rs0, 2);
            rs1 += __shfl_xor_sync(0xffffffffu, rs1, 1);
            rs1 += __shfl_xor_sync(0xffffffffu, rs1, 2);
            if ((lane & 3) == 0) {
                atomicAdd(&jp[wm + im * 16 + qr][jj], rs0);
                atomicAdd(&jp[wm + im * 16 + qr + 8][jj], rs1);
            }
        }
        __syncthreads();
        if (tid < 256) {
            int rl = tid >> 1, j = tid & 1;
            float jsum = jp[rl][j];
            float e = expf(jsum * (1.0f / 32.0f) - 1.0f - kddm[j]);
            es[rl][j] = e;
            g_e[(m0 + rl) * NJ + j0 + j] = e;
            atomicAdd(&g_Z[m0 + rl], e);
        }
        __syncthreads();
        #pragma unroll
        for (int im = 0; im < 4; im++) {
            int rl = wm + im * 16 + qr;
            int r0g = m0 + rl;
            float e0 = es[rl][jj], e1 = es[rl + 8][jj];
            #pragma unroll
            for (int in = 0; in < 4; in++) {
                int cg = n0 + wn + in * 8 + qc;
                float* c = acc[im][in];
                *(__nv_bfloat162*)&g_A2[(size_t)r0g * JM + cg] =
                    __floats2bfloat162_rn(c[0] * e0, c[1] * e0);
                *(__nv_bfloat162*)&g_A2[(size_t)(r0g + 8) * JM + cg] =
                    __floats2bfloat162_rn(c[2] * e1, c[3] * e1);
            }
        }
        __syncthreads();
        if (tid == 0) {
            __threadfence();
            atomicAdd(&g_band[by], 1);
        }
        return;
    }

    // ---------------- gemm2 tile block (BK=32, 3-stage) -------------------
    {
        __shared__ __align__(16) __nv_bfloat16 Ae[128][24];
        __shared__ __align__(16) __nv_bfloat16 Be[64][24];
        const int t = bid - 1024;
        const int nx = t & 7, my = t >> 3;
        const int wm = (wid >> 1) * 32;
        const int wn = (wid & 1) * 32;
        const int m0 = my * 128;
        const int n0 = nx * 64;

        if (tid == 0) {
            while (atomicAdd(&g_band[my], 0) < 8) { }
        }
        __syncthreads();
        __threadfence();

        for (int idx = tid; idx < 128 * 16; idx += 256) {
            int rr = idx >> 4, j = idx & 15;
            Ae[rr][j] = __float2bfloat16(*((volatile float*)&g_e[(size_t)(m0 + rr) * NJ + j]));
            if (rr < 64) Be[rr][j] = __float2bfloat16(bvec[(size_t)j * NU + n0 + rr]);
        }

        uint32_t Bs_base = base + 24576;
        uint32_t Ae_base = (uint32_t)__cvta_generic_to_shared(Ae);
        uint32_t Be_base = (uint32_t)__cvta_generic_to_shared(Be);

        int arow[2], asw[2];
        #pragma unroll
        for (int im = 0; im < 2; im++) { arow[im] = wm + im * 16 + rlo; asw[im] = (arow[im] >> 1) & 3; }

        float acc[2][4][4] = {};

        auto load_stage = [&](int ki, int s) {
            const __nv_bfloat16* asrc = g_A2 + (size_t)m0 * JM + ki * 32;
            const __nv_bfloat16* bsrc = g_Wb + (size_t)ki * 32 * NU + n0;
            uint32_t a_s = base + s * 8192;
            uint32_t b_s = Bs_base + s * 4096;
            #pragma unroll
            for (int i = 0; i < 2; i++) {
                int lin = tid + i * 256;
                int r = lin >> 2, c = lin & 3;
                cp16(a_s + r * 64 + ((c ^ ((r >> 1) & 3)) << 4),
                     asrc + (size_t)r * JM + c * 8);
            }
            {
                int r = tid >> 3, c = tid & 7;
                cp16(b_s + r * 128 + ((c ^ (r & 7)) << 4),
                     bsrc + (size_t)r * NU + c * 8);
            }
            cp_commit();
        };

        auto compute = [&](int s) {
            uint32_t a_s = base + s * 8192;
            uint32_t b_s = Bs_base + s * 4096;
            #pragma unroll
            for (int kk = 0; kk < 2; kk++) {
                int ch = kk * 2 + chi;
                uint32_t a[2][4], b[2][4];
                #pragma unroll
                for (int im = 0; im < 2; im++)
                    ldm_x4(a[im], a_s + arow[im] * 64 + ((ch ^ asw[im]) << 4));
                #pragma unroll
                for (int ib = 0; ib < 2; ib++) {
                    int row = kk * 16 + rlo;
                    int cb = (wn >> 3) + ib * 2 + chi;
                    ldm_x4t(b[ib], b_s + row * 128 + ((cb ^ (row & 7)) << 4));
                }
                #pragma unroll
                for (int im = 0; im < 2; im++) {
                    mma_bf16(acc[im][0], a[im], b[0][0], b[0][1]);
                    mma_bf16(acc[im][1], a[im], b[0][2], b[0][3]);
                    mma_bf16(acc[im][2], a[im], b[1][0], b[1][1]);
                    mma_bf16(acc[im][3], a[im], b[1][2], b[1][3]);
                }
            }
        };

        load_stage(0, 0);
        load_stage(1, 1);
        #pragma unroll 1
        for (int ki = 0; ki < 32; ki++) {
            if (ki < 31) cp_wait<1>(); else cp_wait<0>();
            __syncthreads();
            if (ki + 2 < 32) load_stage(ki + 2, (ki + 2) % 3);
            compute(ki % 3);
        }

        // bias fold
        {
            uint32_t b[2][4];
            #pragma unroll
            for (int ib = 0; ib < 2; ib++) {
                int row = wn + ib * 16 + rlo;
                ldm_x4(b[ib], Be_base + row * 48 + chi * 16);
            }
            #pragma unroll
            for (int im = 0; im < 2; im++) {
                uint32_t a[4];
                int row = wm + im * 16 + rlo;
                ldm_x4(a, Ae_base + row * 48 + chi * 16);
                mma_bf16(acc[im][0], a, b[0][0], b[0][2]);
                mma_bf16(acc[im][1], a, b[0][1], b[0][3]);
                mma_bf16(acc[im][2], a, b[1][0], b[1][2]);
                mma_bf16(acc[im][3], a, b[1][1], b[1][3]);
            }
        }

        const int qr = lane >> 2;
        const int qc = (lane & 3) * 2;
        #pragma unroll
        for (int im = 0; im < 2; im++) {
            int r0g = m0 + wm + im * 16 + qr;
            float zi0 = 1.0f / *((volatile float*)&g_Z[r0g]);
            float zi1 = 1.0f / *((volatile float*)&g_Z[r0g + 8]);
            #pragma unroll
            for (int in = 0; in < 4; in++) {
                int cg = n0 + wn + in * 8 + qc;
                float* c = acc[im][in];
                float2 v0 = {c[0] * zi0, c[1] * zi0};
                float2 v1 = {c[2] * zi1, c[3] * zi1};
                *(float2*)&out[(size_t)r0g * NU + cg] = v0;
                *(float2*)&out[(size_t)(r0g + 8) * NU + cg] = v1;
            }
        }
    }
}

// ============================================================
extern "C" void kernel_launch(void* const* d_in, const int* in_sizes, int n_in,
                              void* d_out, int out_size) {
    const float* h    = (const float*)d_in[0];   // [B, F]
    const float* dom  = (const float*)d_in[1];   // [J, M, F]
    const float* W    = (const float*)d_in[2];   // [J, M, U]
    const float* bvec = (const float*)d_in[3];   // [J, U]
    float* out = (float*)d_out;                  // [B, U]

    cudaFuncSetAttribute(front_kernel, cudaFuncAttributeMaxDynamicSharedMemorySize, 32768);
    cudaFuncSetAttribute(uber_kernel,  cudaFuncAttributeMaxDynamicSharedMemorySize, 49152);

    front_kernel<<<NJ + 640 + 1, 256, 32768>>>(h, dom);
    uber_kernel<<<1280, 256, 49152>>>(h, dom, W, bvec, out);
}